// round 5
// baseline (speedup 1.0000x reference)
#include <cuda_runtime.h>
#include <cuda_bf16.h>
#include <cstdint>
#include <cstddef>

// ---------------- problem constants ----------------
#define BB   4
#define TT   2048
#define HIDD 2048
#define HH   16
#define DKK  128
#define DVV  128
#define NBT  (BB*TT)           // 8192 rows
static constexpr float SCALE_F = 0.08838834764831845f;  // 128^-0.5
static constexpr float EPS_F   = 1e-5f;

// ---------------- scratch (device globals; no allocation allowed) ----------------
#define BUFE ((size_t)NBT * HIDD)      // 16.78M elems
#define WE   ((size_t)HIDD * HIDD)     // 4.19M elems
__device__ float         g_scratch[BUFE * 9 + (size_t)NBT * HH];
__device__ __nv_bfloat16 g_bf[BUFE * 4 + WE * 12];

__device__ __forceinline__ float sigmoidf_(float x) { return 1.f / (1.f + expf(-x)); }

__device__ __forceinline__ uint32_t smem_u32(const void* p) {
    uint32_t a;
    asm("{ .reg .u64 t; cvta.to.shared.u64 t, %1; cvt.u32.u64 %0, t; }" : "=r"(a) : "l"(p));
    return a;
}
__device__ __forceinline__ void cp16(uint32_t dst, const void* src) {
    asm volatile("cp.async.cg.shared.global [%0], [%1], 16;" :: "r"(dst), "l"(src));
}
__device__ __forceinline__ void cp_commit() {
    asm volatile("cp.async.commit_group;" ::: "memory");
}
__device__ __forceinline__ void ldsm4(uint32_t* r, uint32_t addr) {
    asm volatile("ldmatrix.sync.aligned.m8n8.x4.shared.b16 {%0,%1,%2,%3}, [%4];"
                 : "=r"(r[0]), "=r"(r[1]), "=r"(r[2]), "=r"(r[3]) : "r"(addr));
}
__device__ __forceinline__ void mma16816(float* c, const uint32_t* a, uint32_t b0, uint32_t b1) {
    asm volatile("mma.sync.aligned.m16n8k16.row.col.f32.bf16.bf16.f32 "
                 "{%0,%1,%2,%3}, {%4,%5,%6,%7}, {%8,%9}, {%0,%1,%2,%3};"
                 : "+f"(c[0]), "+f"(c[1]), "+f"(c[2]), "+f"(c[3])
                 : "r"(a[0]), "r"(a[1]), "r"(a[2]), "r"(a[3]), "r"(b0), "r"(b1));
}

// ---- packed f32x2 helpers (Blackwell, base sm_100 PTX) ----
__device__ __forceinline__ uint64_t f32x2_fma(uint64_t a, uint64_t b, uint64_t c) {
    uint64_t d;
    asm("fma.rn.f32x2 %0, %1, %2, %3;" : "=l"(d) : "l"(a), "l"(b), "l"(c));
    return d;
}
__device__ __forceinline__ uint64_t f32x2_mul(uint64_t a, uint64_t b) {
    uint64_t d;
    asm("mul.rn.f32x2 %0, %1, %2;" : "=l"(d) : "l"(a), "l"(b));
    return d;
}
__device__ __forceinline__ uint64_t pack2(float x) {
    uint64_t d; uint32_t u = __float_as_uint(x);
    asm("mov.b64 %0, {%1, %1};" : "=l"(d) : "r"(u));
    return d;
}
__device__ __forceinline__ float unpack_sum(uint64_t p) {
    uint32_t lo, hi;
    asm("mov.b64 {%0, %1}, %2;" : "=r"(lo), "=r"(hi) : "l"(p));
    return __uint_as_float(lo) + __uint_as_float(hi);
}
__device__ __forceinline__ void lds_v2u64(uint64_t& a, uint64_t& b, uint32_t addr) {
    asm volatile("ld.shared.v2.u64 {%0, %1}, [%2];" : "=l"(a), "=l"(b) : "r"(addr));
}

// ======================================================================
// mma.sync GEMM: C[8192,2048] = A[8192,2048] @ W[2048,2048], bf16x3 split.
// A as (Ahi, Alo) [M,K] bf16 row-major; W as (Bhi, Blo) [N,K] bf16 (= W^T).
// CTA tile 128x128, BK=64, 8 warps (warp tile 32x64), 3-stage cp.async
// pipeline, prefetch-before-compute, one barrier per chunk.
// epi: 0 = none, 1 = sigmoid(acc + bias[col]) (bias may be null)
// ======================================================================
#define GK     2048
#define BK     64
#define NCH    (GK / BK)          // 32
#define SM_AH  0
#define SM_AL  (16 * 1024)
#define SM_BH  (32 * 1024)
#define SM_BL  (48 * 1024)
#define STAGE  (64 * 1024)
#define NSTAGE 3
#define SMEM_GEMM (NSTAGE * STAGE)     // 196608

__global__ void __launch_bounds__(256, 1)
gemm_bf16x3_kernel(const __nv_bfloat16* __restrict__ Ahi, const __nv_bfloat16* __restrict__ Alo,
                   const __nv_bfloat16* __restrict__ Bhi, const __nv_bfloat16* __restrict__ Blo,
                   const float* __restrict__ bias, float* __restrict__ C, int epi)
{
    extern __shared__ __align__(1024) char sm[];
    const uint32_t smb = smem_u32(sm);

    const int tid  = threadIdx.x;
    const int wid  = tid >> 5;
    const int lane = tid & 31;
    const int bm   = blockIdx.y * 128;
    const int bn   = blockIdx.x * 128;
    const int wm   = wid & 3;       // M group (4 x 32 rows)
    const int wn   = wid >> 2;      // N group (2 x 64 cols)

    const __nv_bfloat16* Ah = Ahi + (size_t)bm * GK;
    const __nv_bfloat16* Al = Alo + (size_t)bm * GK;
    const __nv_bfloat16* Bh = Bhi + (size_t)bn * GK;
    const __nv_bfloat16* Bl = Blo + (size_t)bn * GK;

    auto prefetch = [&](int st, int k0) {
        const uint32_t base = smb + st * STAGE;
        #pragma unroll
        for (int i = 0; i < 4; i++) {
            const int s   = tid + 256 * i;
            const int row = s >> 3, seg = s & 7;
            const uint32_t sw = row * 128 + ((seg * 16) ^ ((row & 7) << 4));
            const size_t go = (size_t)row * GK + k0 + seg * 8;
            cp16(base + SM_AH + sw, Ah + go);
            cp16(base + SM_AL + sw, Al + go);
            cp16(base + SM_BH + sw, Bh + go);
            cp16(base + SM_BL + sw, Bl + go);
        }
        cp_commit();
    };

    prefetch(0, 0);
    prefetch(1, BK);

    float acc[2][8][4];
    #pragma unroll
    for (int i = 0; i < 2; i++)
        #pragma unroll
        for (int j = 0; j < 8; j++)
            #pragma unroll
            for (int q = 0; q < 4; q++) acc[i][j][q] = 0.f;

    // per-lane ldmatrix address pieces
    const int l16  = lane & 15;
    const uint32_t xorv = (uint32_t)((lane & 7) << 4);
    const uint32_t chalf = (uint32_t)((lane >> 4) * 16);     // byte offset of k-halves
    uint32_t arow128[2], brow128[4];
    #pragma unroll
    for (int mt = 0; mt < 2; mt++) arow128[mt] = (uint32_t)((wm * 32 + mt * 16 + l16) * 128);
    #pragma unroll
    for (int nt = 0; nt < 4; nt++) brow128[nt] = (uint32_t)((wn * 64 + nt * 16 + l16) * 128);

    int slot = 0, pslot = 2;
    for (int c = 0; c < NCH; c++) {
        if (c + 1 < NCH) asm volatile("cp.async.wait_group 1;" ::: "memory");
        else             asm volatile("cp.async.wait_group 0;" ::: "memory");
        __syncthreads();
        // prefetch BEFORE compute: writes slot (c+2)%3 (the slot consumed in
        // iter c-1; all readers passed the barrier above)
        if (c + 2 < NCH) {
            prefetch(pslot, (c + 2) * BK);
        }

        const uint32_t base = smb + slot * STAGE;
        #pragma unroll
        for (int kk = 0; kk < 4; kk++) {
            const uint32_t koff = kk * 32 + chalf;
            uint32_t ah[2][4], al[2][4];
            #pragma unroll
            for (int mt = 0; mt < 2; mt++) {
                const uint32_t off = arow128[mt] + (koff ^ xorv);
                ldsm4(ah[mt], base + SM_AH + off);
                ldsm4(al[mt], base + SM_AL + off);
            }
            #pragma unroll
            for (int nt = 0; nt < 4; nt++) {
                const uint32_t boff = brow128[nt] + (koff ^ xorv);
                uint32_t bh[4], bl[4];
                ldsm4(bh, base + SM_BH + boff);
                ldsm4(bl, base + SM_BL + boff);
                #pragma unroll
                for (int mt = 0; mt < 2; mt++) {
                    mma16816(acc[mt][nt * 2],     ah[mt], bh[0], bh[2]);
                    mma16816(acc[mt][nt * 2 + 1], ah[mt], bh[1], bh[3]);
                    mma16816(acc[mt][nt * 2],     al[mt], bh[0], bh[2]);
                    mma16816(acc[mt][nt * 2 + 1], al[mt], bh[1], bh[3]);
                    mma16816(acc[mt][nt * 2],     ah[mt], bl[0], bl[2]);
                    mma16816(acc[mt][nt * 2 + 1], ah[mt], bl[1], bl[3]);
                }
            }
        }
        slot  = (slot  + 1) % NSTAGE;
        pslot = (pslot + 1) % NSTAGE;
    }

    // epilogue
    #pragma unroll
    for (int mt = 0; mt < 2; mt++) {
        const int r0 = bm + wm * 32 + mt * 16 + (lane >> 2);
        #pragma unroll
        for (int j = 0; j < 8; j++) {
            const int cc = bn + wn * 64 + j * 8 + (lane & 3) * 2;
            float v0 = acc[mt][j][0], v1 = acc[mt][j][1];
            float v2 = acc[mt][j][2], v3 = acc[mt][j][3];
            if (epi == 1) {
                const float b0 = bias ? bias[cc]     : 0.f;
                const float b1 = bias ? bias[cc + 1] : 0.f;
                v0 = sigmoidf_(v0 + b0); v1 = sigmoidf_(v1 + b1);
                v2 = sigmoidf_(v2 + b0); v3 = sigmoidf_(v3 + b1);
            }
            *(float2*)(C + (size_t)r0 * HIDD + cc)       = make_float2(v0, v1);
            *(float2*)(C + (size_t)(r0 + 8) * HIDD + cc) = make_float2(v2, v3);
        }
    }
}

// ======================================================================
// elementwise fp32 -> (bf16 hi, bf16 lo)
// ======================================================================
__global__ void split_kernel(const float* __restrict__ in,
                             __nv_bfloat16* __restrict__ hi, __nv_bfloat16* __restrict__ lo)
{
    const size_t i = (size_t)blockIdx.x * blockDim.x + threadIdx.x;
    const float v = in[i];
    const __nv_bfloat16 h = __float2bfloat16(v);
    hi[i] = h;
    lo[i] = __float2bfloat16(v - __bfloat162float(h));
}

// ======================================================================
// all six W [K=2048, N=2048] f32 -> W^T hi/lo [N, K] bf16 in ONE launch
// (also makes launch #6 a GEMM so ncu -s 5 -c 1 captures the GEMM)
// ======================================================================
struct WSet {
    const float* src[6];
    __nv_bfloat16* hi[6];
    __nv_bfloat16* lo[6];
};
__global__ void transpose_split_all_kernel(WSet ws)
{
    __shared__ float tile[32][33];
    const int z  = blockIdx.z;
    const float* W = ws.src[z];
    __nv_bfloat16* hi = ws.hi[z];
    __nv_bfloat16* lo = ws.lo[z];
    const int tx = threadIdx.x, ty = threadIdx.y;     // (32, 8)
    const int x0 = blockIdx.x * 32, y0 = blockIdx.y * 32;
    #pragma unroll
    for (int j = 0; j < 32; j += 8)
        tile[ty + j][tx] = W[(size_t)(y0 + ty + j) * HIDD + x0 + tx];
    __syncthreads();
    #pragma unroll
    for (int j = 0; j < 32; j += 8) {
        const float v = tile[tx][ty + j];
        const __nv_bfloat16 h = __float2bfloat16(v);
        const size_t o = (size_t)(x0 + ty + j) * HIDD + y0 + tx;
        hi[o] = h;
        lo[o] = __float2bfloat16(v - __bfloat162float(h));
    }
}

// ======================================================================
// beta = sigmoid(x @ Wb + bb)
// ======================================================================
__global__ void beta_kernel(const float* __restrict__ x, const float* __restrict__ Wb,
                            const float* __restrict__ bb, float* __restrict__ out)
{
    const int row = blockIdx.x * 16 + (threadIdx.x >> 4);
    const int col = threadIdx.x & 15;
    const float* xr = x + (size_t)row * HIDD;
    float acc = 0.f;
    for (int k = 0; k < HIDD; k += 4) {
        float4 xv = *(const float4*)(xr + k);
        acc += xv.x * Wb[(k + 0) * HH + col];
        acc += xv.y * Wb[(k + 1) * HH + col];
        acc += xv.z * Wb[(k + 2) * HH + col];
        acc += xv.w * Wb[(k + 3) * HH + col];
    }
    out[(size_t)row * HH + col] = sigmoidf_(acc + bb[col]);
}

// ======================================================================
// causal depthwise conv (K=4) + bias + SiLU (+scale)
// ======================================================================
__global__ void conv_silu_kernel(const float* __restrict__ u, const float* __restrict__ w,
                                 const float* __restrict__ bias, float* __restrict__ y,
                                 float scale)
{
    const size_t gid = (size_t)blockIdx.x * blockDim.x + threadIdx.x;
    const int c  = (int)(gid & (HIDD - 1));
    const size_t bt = gid >> 11;
    const int t  = (int)(bt & (TT - 1));
    float acc = bias[c];
    const float* up = u + gid;
    #pragma unroll
    for (int j = 0; j < 4; j++) {
        const int ttc = t - 3 + j;
        if (ttc >= 0) acc += w[c * 4 + j] * up[(ptrdiff_t)(j - 3) * HIDD];
    }
    const float sv = acc * sigmoidf_(acc);
    y[gid] = sv * scale;
}

// ======================================================================
// Delta-rule scan with packed f32x2 math.
// 128 blocks x 256 threads; thread = (v in 0..63, 32-k chunk as 16 f32x2).
// ======================================================================
__global__ void __launch_bounds__(256, 1) scan_kernel(
    const float* __restrict__ q, const float* __restrict__ k,
    const float* __restrict__ v, const float* __restrict__ a,
    const float* __restrict__ beta, float* __restrict__ o)
{
    __shared__ __align__(16) float ksm[2][4 * 36];
    __shared__ __align__(16) float qsm[2][4 * 36];
    __shared__ float vsm[2][64];
    __shared__ float gsm[2][64];
    __shared__ float bsm[2];

    const int blk  = blockIdx.x;
    const int b    = blk >> 5;
    const int h    = (blk >> 1) & 15;
    const int half = blk & 1;

    const int tid = threadIdx.x;
    const int vl  = tid >> 2;
    const int c   = tid & 3;
    const int vg  = half * 64 + vl;

    const int lc  = tid & 127;
    const int lsm = (lc >> 5) * 36 + (lc & 31);

    const size_t baseQK = (size_t)b * TT * HIDD + h * DKK;
    const size_t baseVA = (size_t)b * TT * HIDD + h * DVV;

    uint64_t s2[16];
    #pragma unroll
    for (int i = 0; i < 16; i++) s2[i] = 0ull;

    // per-thread smem base addrs for the two buffers (16B aligned)
    uint32_t kaddr[2], qaddr[2];
    #pragma unroll
    for (int bb2 = 0; bb2 < 2; bb2++) {
        kaddr[bb2] = smem_u32(&ksm[bb2][c * 36]);
        qaddr[bb2] = smem_u32(&qsm[bb2][c * 36]);
    }

    if (tid < 128) ksm[0][lsm] = k[baseQK + lc];
    else           qsm[0][lsm] = q[baseQK + lc];
    if (tid < 64)            vsm[0][tid]      = v[baseVA + half * 64 + tid];
    else if (tid < 128)      gsm[0][tid - 64] = a[baseVA + half * 64 + (tid - 64)];
    if (tid == 0)            bsm[0] = beta[(size_t)b * TT * HH + h];

    for (int t = 0; t < TT; t++) {
        const int buf = t & 1;
        __syncthreads();

        const float av = gsm[buf][vl];
        const float vt = vsm[buf][vl];
        const float bt = bsm[buf];

        uint64_t kf2[16], q2[16];
        #pragma unroll
        for (int j = 0; j < 8; j++)
            lds_v2u64(kf2[2 * j], kf2[2 * j + 1], kaddr[buf] + j * 16);
        #pragma unroll
        for (int j = 0; j < 8; j++)
            lds_v2u64(q2[2 * j], q2[2 * j + 1], qaddr[buf] + j * 16);

        // sk = S . k (partial over 32 dims = 16 pairs)
        uint64_t sk2 = 0ull;
        #pragma unroll
        for (int i = 0; i < 16; i++) sk2 = f32x2_fma(s2[i], kf2[i], sk2);
        float sk = unpack_sum(sk2);
        sk += __shfl_xor_sync(0xffffffffu, sk, 1);
        sk += __shfl_xor_sync(0xffffffffu, sk, 2);

        const float d  = bt * (sk - vt);
        const uint64_t dn2 = pack2(-d);
        const uint64_t av2 = pack2(av);

        uint64_t op2 = 0ull;
        #pragma unroll
        for (int i = 0; i < 16; i++) {
            const uint64_t nt = f32x2_mul(dn2, kf2[i]);
            s2[i] = f32x2_fma(av2, s2[i], nt);
            op2   = f32x2_fma(s2[i], q2[i], op2);
        }
        float op = unpack_sum(op2);
        op += __shfl_xor_sync(0xffffffffu, op, 1);
        op += __shfl_xor_sync(0xffffffffu, op, 2);
        if (c == 0)
            o[(size_t)(b * TT + t) * HIDD + h * DKK + vg] = op;

        if (t + 1 < TT) {
            const size_t off = (size_t)(t + 1) * HIDD;
            const int nb = buf ^ 1;
            if (tid < 128) ksm[nb][lsm] = k[baseQK + off + lc];
            else           qsm[nb][lsm] = q[baseQK + off + lc];
            if (tid < 64)        vsm[nb][tid]      = v[baseVA + off + half * 64 + tid];
            else if (tid < 128)  gsm[nb][tid - 64] = a[baseVA + off + half * 64 + (tid - 64)];
            if (tid == 0)        bsm[nb] = beta[(size_t)(b * TT + t + 1) * HH + h];
        }
    }
}

// ======================================================================
// LayerNorm over DV=128 + gate, output split to bf16 hi/lo (final GEMM A)
// ======================================================================
__global__ void ln_gate_kernel(const float* __restrict__ o, const float* __restrict__ g,
                               const float* __restrict__ lnw, const float* __restrict__ lnb,
                               __nv_bfloat16* __restrict__ ghi, __nv_bfloat16* __restrict__ glo)
{
    const int gw   = (int)(((size_t)blockIdx.x * blockDim.x + threadIdx.x) >> 5);
    const int lane = threadIdx.x & 31;
    const size_t base = (size_t)gw * 128 + lane * 4;
    float4 x = *(const float4*)(o + base);
    float s  = x.x + x.y + x.z + x.w;
    float ss = x.x * x.x + x.y * x.y + x.z * x.z + x.w * x.w;
    #pragma unroll
    for (int m = 16; m > 0; m >>= 1) {
        s  += __shfl_xor_sync(0xffffffffu, s,  m);
        ss += __shfl_xor_sync(0xffffffffu, ss, m);
    }
    const float mu  = s * (1.f / 128.f);
    const float var = ss * (1.f / 128.f) - mu * mu;
    const float inv = rsqrtf(var + EPS_F);
    const float4 wv = *(const float4*)(lnw + lane * 4);
    const float4 bv = *(const float4*)(lnb + lane * 4);
    const float4 gv = *(const float4*)(g + base);
    float r[4];
    r[0] = ((x.x - mu) * inv * wv.x + bv.x) * gv.x;
    r[1] = ((x.y - mu) * inv * wv.y + bv.y) * gv.y;
    r[2] = ((x.z - mu) * inv * wv.z + bv.z) * gv.z;
    r[3] = ((x.w - mu) * inv * wv.w + bv.w) * gv.w;
    __nv_bfloat16 h[4], l[4];
    #pragma unroll
    for (int i = 0; i < 4; i++) {
        h[i] = __float2bfloat16(r[i]);
        l[i] = __float2bfloat16(r[i] - __bfloat162float(h[i]));
    }
    *(__nv_bfloat162*)(ghi + base)     = __nv_bfloat162(h[0], h[1]);
    *(__nv_bfloat162*)(ghi + base + 2) = __nv_bfloat162(h[2], h[3]);
    *(__nv_bfloat162*)(glo + base)     = __nv_bfloat162(l[0], l[1]);
    *(__nv_bfloat162*)(glo + base + 2) = __nv_bfloat162(l[2], l[3]);
}

// ======================================================================
// launch
// ======================================================================
extern "C" void kernel_launch(void* const* d_in, const int* in_sizes, int n_in,
                              void* d_out, int out_size)
{
    const float* x       = (const float*)d_in[0];
    const float* Wq      = (const float*)d_in[1];
    const float* Wk      = (const float*)d_in[2];
    const float* Wv      = (const float*)d_in[3];
    const float* Wa      = (const float*)d_in[4];
    const float* ba      = (const float*)d_in[5];
    const float* Wb      = (const float*)d_in[6];
    const float* bb      = (const float*)d_in[7];
    const float* Wg      = (const float*)d_in[8];
    const float* Wo      = (const float*)d_in[9];
    const float* qconv_w = (const float*)d_in[10];
    const float* qconv_b = (const float*)d_in[11];
    const float* kconv_w = (const float*)d_in[12];
    const float* kconv_b = (const float*)d_in[13];
    const float* vconv_w = (const float*)d_in[14];
    const float* vconv_b = (const float*)d_in[15];
    const float* ln_w    = (const float*)d_in[16];
    const float* ln_b    = (const float*)d_in[17];

    void* sp = nullptr;
    cudaGetSymbolAddress(&sp, g_scratch);
    float* fb = (float*)sp;
    float* d_qpre = fb + 0 * BUFE;
    float* d_kpre = fb + 1 * BUFE;
    float* d_vpre = fb + 2 * BUFE;
    float* d_q    = fb + 3 * BUFE;
    float* d_k    = fb + 4 * BUFE;
    float* d_v    = fb + 5 * BUFE;
    float* d_a    = fb + 6 * BUFE;
    float* d_g    = fb + 7 * BUFE;
    float* d_o    = fb + 8 * BUFE;
    float* d_beta = fb + 9 * BUFE;

    void* bp = nullptr;
    cudaGetSymbolAddress(&bp, g_bf);
    __nv_bfloat16* hb = (__nv_bfloat16*)bp;
    __nv_bfloat16* xhi = hb + 0 * BUFE;
    __nv_bfloat16* xlo = hb + 1 * BUFE;
    __nv_bfloat16* ghi = hb + 2 * BUFE;
    __nv_bfloat16* glo = hb + 3 * BUFE;
    __nv_bfloat16* wt  = hb + 4 * BUFE;       // 12 x WE: (hi,lo) x {q,k,v,a,g,o}
    __nv_bfloat16* Wq_hi = wt + 0 * WE, *Wq_lo = wt + 1 * WE;
    __nv_bfloat16* Wk_hi = wt + 2 * WE, *Wk_lo = wt + 3 * WE;
    __nv_bfloat16* Wv_hi = wt + 4 * WE, *Wv_lo = wt + 5 * WE;
    __nv_bfloat16* Wa_hi = wt + 6 * WE, *Wa_lo = wt + 7 * WE;
    __nv_bfloat16* Wg_hi = wt + 8 * WE, *Wg_lo = wt + 9 * WE;
    __nv_bfloat16* Wo_hi = wt + 10 * WE, *Wo_lo = wt + 11 * WE;

    cudaFuncSetAttribute(gemm_bf16x3_kernel,
                         cudaFuncAttributeMaxDynamicSharedMemorySize, SMEM_GEMM);

    // ---- operand prep (launches 1-3) ----
    split_kernel<<<(int)(BUFE / 256), 256>>>(x, xhi, xlo);

    WSet ws;
    ws.src[0] = Wq; ws.hi[0] = Wq_hi; ws.lo[0] = Wq_lo;
    ws.src[1] = Wk; ws.hi[1] = Wk_hi; ws.lo[1] = Wk_lo;
    ws.src[2] = Wv; ws.hi[2] = Wv_hi; ws.lo[2] = Wv_lo;
    ws.src[3] = Wa; ws.hi[3] = Wa_hi; ws.lo[3] = Wa_lo;
    ws.src[4] = Wg; ws.hi[4] = Wg_hi; ws.lo[4] = Wg_lo;
    ws.src[5] = Wo; ws.hi[5] = Wo_hi; ws.lo[5] = Wo_lo;
    transpose_split_all_kernel<<<dim3(HIDD / 32, HIDD / 32, 6), dim3(32, 8)>>>(ws);

    beta_kernel<<<NBT / 16, 256>>>(x, Wb, bb, d_beta);

    // ---- 5 projections on tensor cores (launches 4-8; #6 = gemmV for ncu) ----
    const dim3 gg(HIDD / 128, NBT / 128);     // (16, 64)
    gemm_bf16x3_kernel<<<gg, 256, SMEM_GEMM>>>(xhi, xlo, Wq_hi, Wq_lo, nullptr, d_qpre, 0);
    gemm_bf16x3_kernel<<<gg, 256, SMEM_GEMM>>>(xhi, xlo, Wk_hi, Wk_lo, nullptr, d_kpre, 0);
    gemm_bf16x3_kernel<<<gg, 256, SMEM_GEMM>>>(xhi, xlo, Wv_hi, Wv_lo, nullptr, d_vpre, 0);
    gemm_bf16x3_kernel<<<gg, 256, SMEM_GEMM>>>(xhi, xlo, Wa_hi, Wa_lo, ba,      d_a,    1);
    gemm_bf16x3_kernel<<<gg, 256, SMEM_GEMM>>>(xhi, xlo, Wg_hi, Wg_lo, nullptr, d_g,    1);

    const int convBlocks = (int)((size_t)NBT * HIDD / 256);
    conv_silu_kernel<<<convBlocks, 256>>>(d_qpre, qconv_w, qconv_b, d_q, 1.f);
    conv_silu_kernel<<<convBlocks, 256>>>(d_kpre, kconv_w, kconv_b, d_k, SCALE_F);
    conv_silu_kernel<<<convBlocks, 256>>>(d_vpre, vconv_w, vconv_b, d_v, 1.f);

    scan_kernel<<<BB * HH * 2, 256>>>(d_q, d_k, d_v, d_a, d_beta, d_o);

    ln_gate_kernel<<<(NBT * HH) / 8, 256>>>(d_o, d_g, ln_w, ln_b, ghi, glo);

    gemm_bf16x3_kernel<<<gg, 256, SMEM_GEMM>>>(ghi, glo, Wo_hi, Wo_lo, nullptr, (float*)d_out, 0);

    (void)in_sizes; (void)n_in; (void)out_size;
}

// round 6
// speedup vs baseline: 1.4112x; 1.4112x over previous
#include <cuda_runtime.h>
#include <cuda_bf16.h>
#include <cstdint>
#include <cstddef>

// ---------------- problem constants ----------------
#define BB   4
#define TT   2048
#define HIDD 2048
#define HH   16
#define DKK  128
#define DVV  128
#define NBT  (BB*TT)           // 8192 rows
static constexpr float SCALE_F = 0.08838834764831845f;  // 128^-0.5
static constexpr float EPS_F   = 1e-5f;

// ---------------- scratch (device globals; no allocation allowed) ----------------
#define BUFE ((size_t)NBT * HIDD)      // 16.78M elems
#define WE   ((size_t)HIDD * HIDD)     // 4.19M elems
__device__ float         g_scratch[BUFE * 9 + (size_t)NBT * HH];
__device__ __nv_bfloat16 g_bf[BUFE * 4 + WE * 12];

__device__ __forceinline__ float sigmoidf_(float x) { return 1.f / (1.f + expf(-x)); }

__device__ __forceinline__ uint32_t smem_u32(const void* p) {
    uint32_t a;
    asm("{ .reg .u64 t; cvta.to.shared.u64 t, %1; cvt.u32.u64 %0, t; }" : "=r"(a) : "l"(p));
    return a;
}
__device__ __forceinline__ void cp16(uint32_t dst, const void* src) {
    asm volatile("cp.async.cg.shared.global [%0], [%1], 16;" :: "r"(dst), "l"(src));
}
__device__ __forceinline__ void cp_commit() {
    asm volatile("cp.async.commit_group;" ::: "memory");
}
__device__ __forceinline__ void ldsm4(uint32_t* r, uint32_t addr) {
    asm volatile("ldmatrix.sync.aligned.m8n8.x4.shared.b16 {%0,%1,%2,%3}, [%4];"
                 : "=r"(r[0]), "=r"(r[1]), "=r"(r[2]), "=r"(r[3]) : "r"(addr));
}
__device__ __forceinline__ void mma16816(float* c, const uint32_t* a, uint32_t b0, uint32_t b1) {
    asm volatile("mma.sync.aligned.m16n8k16.row.col.f32.bf16.bf16.f32 "
                 "{%0,%1,%2,%3}, {%4,%5,%6,%7}, {%8,%9}, {%0,%1,%2,%3};"
                 : "+f"(c[0]), "+f"(c[1]), "+f"(c[2]), "+f"(c[3])
                 : "r"(a[0]), "r"(a[1]), "r"(a[2]), "r"(a[3]), "r"(b0), "r"(b1));
}

// ---- packed f32x2 helpers ----
__device__ __forceinline__ uint64_t f32x2_fma(uint64_t a, uint64_t b, uint64_t c) {
    uint64_t d;
    asm("fma.rn.f32x2 %0, %1, %2, %3;" : "=l"(d) : "l"(a), "l"(b), "l"(c));
    return d;
}
__device__ __forceinline__ uint64_t f32x2_mul(uint64_t a, uint64_t b) {
    uint64_t d;
    asm("mul.rn.f32x2 %0, %1, %2;" : "=l"(d) : "l"(a), "l"(b));
    return d;
}
__device__ __forceinline__ uint64_t pack2(float x) {
    uint64_t d; uint32_t u = __float_as_uint(x);
    asm("mov.b64 %0, {%1, %1};" : "=l"(d) : "r"(u));
    return d;
}
__device__ __forceinline__ float unpack_sum(uint64_t p) {
    uint32_t lo, hi;
    asm("mov.b64 {%0, %1}, %2;" : "=r"(lo), "=r"(hi) : "l"(p));
    return __uint_as_float(lo) + __uint_as_float(hi);
}
__device__ __forceinline__ void lds_v2u64(uint64_t& a, uint64_t& b, uint32_t addr) {
    asm volatile("ld.shared.v2.u64 {%0, %1}, [%2];" : "=l"(a), "=l"(b) : "r"(addr));
}

// ======================================================================
// mma.sync GEMM, bf16x3 split, batched over z (up to 5 weights, shared A).
// CTA tile 128x128, BK=32, 3-stage cp.async, 2 CTAs/SM.
// smem per stage: A 128 rows x 128B (hi bytes 0-63 | lo 64-127) = 16KB,
//                 B same = 16KB -> 32KB/stage, 96KB total.
// ======================================================================
#define GK     2048
#define BK     32
#define NCH    (GK / BK)          // 64
#define SM_A   0
#define SM_B   (16 * 1024)
#define STAGE  (32 * 1024)
#define NSTAGE 3
#define SMEM_GEMM (NSTAGE * STAGE)     // 98304

struct GemmBatch {
    const __nv_bfloat16* bh[5];
    const __nv_bfloat16* bl[5];
    const float* bias[5];
    float* C[5];
    int epi[5];
};

__global__ void __launch_bounds__(256, 2)
gemm_bf16x3_kernel(const __nv_bfloat16* __restrict__ Ahi, const __nv_bfloat16* __restrict__ Alo,
                   GemmBatch gb)
{
    extern __shared__ __align__(1024) char sm[];
    const uint32_t smb = smem_u32(sm);

    const int z    = blockIdx.z;
    const int tid  = threadIdx.x;
    const int wid  = tid >> 5;
    const int lane = tid & 31;
    const int bm   = blockIdx.y * 128;
    const int bn   = blockIdx.x * 128;
    const int wm   = wid & 3;       // M group (4 x 32 rows)
    const int wn   = wid >> 2;      // N group (2 x 64 cols)

    const __nv_bfloat16* Ah = Ahi + (size_t)bm * GK;
    const __nv_bfloat16* Al = Alo + (size_t)bm * GK;
    const __nv_bfloat16* Bh = gb.bh[z] + (size_t)bn * GK;
    const __nv_bfloat16* Bl = gb.bl[z] + (size_t)bn * GK;
    const float* bias = gb.bias[z];
    float* C = gb.C[z];
    const int epi = gb.epi[z];

    auto prefetch = [&](int st, int k0) {
        const uint32_t base = smb + st * STAGE;
        #pragma unroll
        for (int i = 0; i < 4; i++) {
            const int s   = tid + 256 * i;
            const int row = s >> 3, seg = s & 7;
            const uint32_t sw = row * 128 + ((seg * 16) ^ ((row & 7) << 4));
            const size_t go = (size_t)row * GK + k0 + (seg & 3) * 8;
            cp16(base + SM_A + sw, (seg < 4 ? Ah : Al) + go);
            cp16(base + SM_B + sw, (seg < 4 ? Bh : Bl) + go);
        }
        cp_commit();
    };

    prefetch(0, 0);
    prefetch(1, BK);

    float acc[2][8][4];
    #pragma unroll
    for (int i = 0; i < 2; i++)
        #pragma unroll
        for (int j = 0; j < 8; j++)
            #pragma unroll
            for (int q = 0; q < 4; q++) acc[i][j][q] = 0.f;

    // per-lane ldmatrix address pieces
    const int l16  = lane & 15;
    const uint32_t xorv  = (uint32_t)((lane & 7) << 4);
    const uint32_t chalf = (uint32_t)((lane >> 4) * 16);
    uint32_t arow128[2], brow128[4];
    #pragma unroll
    for (int mt = 0; mt < 2; mt++) arow128[mt] = (uint32_t)((wm * 32 + mt * 16 + l16) * 128);
    #pragma unroll
    for (int nt = 0; nt < 4; nt++) brow128[nt] = (uint32_t)((wn * 64 + nt * 16 + l16) * 128);

    int slot = 0, pslot = 2;
    for (int c = 0; c < NCH; c++) {
        if (c + 1 < NCH) asm volatile("cp.async.wait_group 1;" ::: "memory");
        else             asm volatile("cp.async.wait_group 0;" ::: "memory");
        __syncthreads();
        if (c + 2 < NCH) prefetch(pslot, (c + 2) * BK);

        const uint32_t base = smb + slot * STAGE;
        #pragma unroll
        for (int kk = 0; kk < 2; kk++) {
            const uint32_t koff  = kk * 32 + chalf;       // hi logical bytes 0..63
            const uint32_t koffL = koff + 64;             // lo logical bytes 64..127
            uint32_t ah[2][4], al[2][4];
            #pragma unroll
            for (int mt = 0; mt < 2; mt++) {
                ldsm4(ah[mt], base + SM_A + arow128[mt] + (koff  ^ xorv));
                ldsm4(al[mt], base + SM_A + arow128[mt] + (koffL ^ xorv));
            }
            #pragma unroll
            for (int nt = 0; nt < 4; nt++) {
                uint32_t bh4[4], bl4[4];
                ldsm4(bh4, base + SM_B + brow128[nt] + (koff  ^ xorv));
                ldsm4(bl4, base + SM_B + brow128[nt] + (koffL ^ xorv));
                #pragma unroll
                for (int mt = 0; mt < 2; mt++) {
                    mma16816(acc[mt][nt * 2],     ah[mt], bh4[0], bh4[2]);
                    mma16816(acc[mt][nt * 2 + 1], ah[mt], bh4[1], bh4[3]);
                    mma16816(acc[mt][nt * 2],     al[mt], bh4[0], bh4[2]);
                    mma16816(acc[mt][nt * 2 + 1], al[mt], bh4[1], bh4[3]);
                    mma16816(acc[mt][nt * 2],     ah[mt], bl4[0], bl4[2]);
                    mma16816(acc[mt][nt * 2 + 1], ah[mt], bl4[1], bl4[3]);
                }
            }
        }
        slot  = (slot  + 1) % NSTAGE;
        pslot = (pslot + 1) % NSTAGE;
    }

    // epilogue
    #pragma unroll
    for (int mt = 0; mt < 2; mt++) {
        const int r0 = bm + wm * 32 + mt * 16 + (lane >> 2);
        #pragma unroll
        for (int j = 0; j < 8; j++) {
            const int cc = bn + wn * 64 + j * 8 + (lane & 3) * 2;
            float v0 = acc[mt][j][0], v1 = acc[mt][j][1];
            float v2 = acc[mt][j][2], v3 = acc[mt][j][3];
            if (epi == 1) {
                const float b0 = bias ? bias[cc]     : 0.f;
                const float b1 = bias ? bias[cc + 1] : 0.f;
                v0 = sigmoidf_(v0 + b0); v1 = sigmoidf_(v1 + b1);
                v2 = sigmoidf_(v2 + b0); v3 = sigmoidf_(v3 + b1);
            }
            *(float2*)(C + (size_t)r0 * HIDD + cc)       = make_float2(v0, v1);
            *(float2*)(C + (size_t)(r0 + 8) * HIDD + cc) = make_float2(v2, v3);
        }
    }
}

// ======================================================================
// elementwise fp32 -> (bf16 hi, bf16 lo), 4 elems/thread
// ======================================================================
__global__ void split_kernel(const float* __restrict__ in,
                             __nv_bfloat16* __restrict__ hi, __nv_bfloat16* __restrict__ lo)
{
    const size_t i = ((size_t)blockIdx.x * blockDim.x + threadIdx.x) * 4;
    const float4 v = *(const float4*)(in + i);
    __nv_bfloat16 h[4], l[4];
    const float* vp = (const float*)&v;
    #pragma unroll
    for (int j = 0; j < 4; j++) {
        h[j] = __float2bfloat16(vp[j]);
        l[j] = __float2bfloat16(vp[j] - __bfloat162float(h[j]));
    }
    *(__nv_bfloat162*)(hi + i)     = __nv_bfloat162(h[0], h[1]);
    *(__nv_bfloat162*)(hi + i + 2) = __nv_bfloat162(h[2], h[3]);
    *(__nv_bfloat162*)(lo + i)     = __nv_bfloat162(l[0], l[1]);
    *(__nv_bfloat162*)(lo + i + 2) = __nv_bfloat162(l[2], l[3]);
}

// ======================================================================
// all six W [K=2048, N=2048] f32 -> W^T hi/lo [N, K] bf16 in ONE launch
// ======================================================================
struct WSet {
    const float* src[6];
    __nv_bfloat16* hi[6];
    __nv_bfloat16* lo[6];
};
__global__ void transpose_split_all_kernel(WSet ws)
{
    __shared__ float tile[32][33];
    const int z  = blockIdx.z;
    const float* W = ws.src[z];
    __nv_bfloat16* hi = ws.hi[z];
    __nv_bfloat16* lo = ws.lo[z];
    const int tx = threadIdx.x, ty = threadIdx.y;     // (32, 8)
    const int x0 = blockIdx.x * 32, y0 = blockIdx.y * 32;
    #pragma unroll
    for (int j = 0; j < 32; j += 8)
        tile[ty + j][tx] = W[(size_t)(y0 + ty + j) * HIDD + x0 + tx];
    __syncthreads();
    #pragma unroll
    for (int j = 0; j < 32; j += 8) {
        const float v = tile[tx][ty + j];
        const __nv_bfloat16 h = __float2bfloat16(v);
        const size_t o = (size_t)(x0 + ty + j) * HIDD + y0 + tx;
        hi[o] = h;
        lo[o] = __float2bfloat16(v - __bfloat162float(h));
    }
}

// ======================================================================
// beta = sigmoid(x @ Wb + bb)
// ======================================================================
__global__ void beta_kernel(const float* __restrict__ x, const float* __restrict__ Wb,
                            const float* __restrict__ bb, float* __restrict__ out)
{
    const int row = blockIdx.x * 16 + (threadIdx.x >> 4);
    const int col = threadIdx.x & 15;
    const float* xr = x + (size_t)row * HIDD;
    float acc = 0.f;
    for (int k = 0; k < HIDD; k += 4) {
        float4 xv = *(const float4*)(xr + k);
        acc += xv.x * Wb[(k + 0) * HH + col];
        acc += xv.y * Wb[(k + 1) * HH + col];
        acc += xv.z * Wb[(k + 2) * HH + col];
        acc += xv.w * Wb[(k + 3) * HH + col];
    }
    out[(size_t)row * HH + col] = sigmoidf_(acc + bb[col]);
}

// ======================================================================
// 3 causal depthwise convs (K=4) + bias + SiLU (+scale) in one launch,
// 4 channels per thread (float4)
// ======================================================================
struct ConvSet {
    const float* u[3];
    const float* w[3];
    const float* b[3];
    float* y[3];
    float scale[3];
};
__global__ void conv_silu_all_kernel(ConvSet cs)
{
    const int z = blockIdx.z;
    const size_t e = ((size_t)blockIdx.x * blockDim.x + threadIdx.x) * 4;
    const int c = (int)(e & (HIDD - 1));
    const int t = (int)((e >> 11) & (TT - 1));
    const float* u = cs.u[z];
    const float* w = cs.w[z];
    float4 acc = *(const float4*)(cs.b[z] + c);
    const float4 w0 = *(const float4*)(w + (size_t)c * 4);
    const float4 w1 = *(const float4*)(w + (size_t)(c + 1) * 4);
    const float4 w2 = *(const float4*)(w + (size_t)(c + 2) * 4);
    const float4 w3 = *(const float4*)(w + (size_t)(c + 3) * 4);
    const float* w0p = (const float*)&w0;
    const float* w1p = (const float*)&w1;
    const float* w2p = (const float*)&w2;
    const float* w3p = (const float*)&w3;
    #pragma unroll
    for (int j = 0; j < 4; j++) {
        if (t - 3 + j >= 0) {
            const float4 u4 = *(const float4*)(u + e + (ptrdiff_t)(j - 3) * HIDD);
            acc.x += w0p[j] * u4.x;
            acc.y += w1p[j] * u4.y;
            acc.z += w2p[j] * u4.z;
            acc.w += w3p[j] * u4.w;
        }
    }
    const float s = cs.scale[z];
    acc.x = acc.x * sigmoidf_(acc.x) * s;
    acc.y = acc.y * sigmoidf_(acc.y) * s;
    acc.z = acc.z * sigmoidf_(acc.z) * s;
    acc.w = acc.w * sigmoidf_(acc.w) * s;
    *(float4*)(cs.y[z] + e) = acc;
}

// ======================================================================
// Delta-rule scan: f32x2 math + two-step-ahead register prefetch.
// 128 blocks x 256 threads; thread = (v in 0..63, 32-k chunk as 16 f32x2).
// ======================================================================
__global__ void __launch_bounds__(256, 1) scan_kernel(
    const float* __restrict__ q, const float* __restrict__ k,
    const float* __restrict__ v, const float* __restrict__ a,
    const float* __restrict__ beta, float* __restrict__ o)
{
    __shared__ __align__(16) float ksm[2][4 * 36];
    __shared__ __align__(16) float qsm[2][4 * 36];
    __shared__ float vsm[2][64];
    __shared__ float gsm[2][64];
    __shared__ float bsm[2];

    const int blk  = blockIdx.x;
    const int b    = blk >> 5;
    const int h    = (blk >> 1) & 15;
    const int half = blk & 1;

    const int tid = threadIdx.x;
    const int vl  = tid >> 2;
    const int c   = tid & 3;
    const int vg  = half * 64 + vl;

    const int lc  = tid & 127;
    const int lsm = (lc >> 5) * 36 + (lc & 31);

    const size_t baseQK = (size_t)b * TT * HIDD + h * DKK;
    const size_t baseVA = (size_t)b * TT * HIDD + h * DVV;

    uint64_t s2[16];
    #pragma unroll
    for (int i = 0; i < 16; i++) s2[i] = 0ull;

    uint32_t kaddr[2], qaddr[2];
    #pragma unroll
    for (int bb2 = 0; bb2 < 2; bb2++) {
        kaddr[bb2] = smem_u32(&ksm[bb2][c * 36]);
        qaddr[bb2] = smem_u32(&qsm[bb2][c * 36]);
    }

    // thread roles: tid<128 -> k elem (lc), tid>=128 -> q elem (lc);
    //               tid<64 -> v elem, tid 64..127 -> a elem; tid==0 -> beta
    // stage t=0 directly into buffer 0
    if (tid < 128) ksm[0][lsm] = k[baseQK + lc];
    else           qsm[0][lsm] = q[baseQK + lc];
    if (tid < 64)            vsm[0][tid]      = v[baseVA + half * 64 + tid];
    else if (tid < 128)      gsm[0][tid - 64] = a[baseVA + half * 64 + (tid - 64)];
    if (tid == 0)            bsm[0] = beta[(size_t)b * TT * HH + h];

    // register set A = data for t=1
    float rA_kq = 0.f, rA_vg = 0.f, rA_b = 0.f;
    {
        const size_t off = (size_t)1 * HIDD;
        rA_kq = (tid < 128) ? k[baseQK + off + lc] : q[baseQK + off + lc];
        if (tid < 64)       rA_vg = v[baseVA + off + half * 64 + tid];
        else if (tid < 128) rA_vg = a[baseVA + off + half * 64 + (tid - 64)];
        if (tid == 0)       rA_b = beta[(size_t)(b * TT + 1) * HH + h];
    }

    for (int t = 0; t < TT; t++) {
        const int buf = t & 1;
        __syncthreads();

        // issue loads for t+2 (non-blocking; consumed at end of iter t+1)
        float rB_kq = 0.f, rB_vg = 0.f, rB_b = 0.f;
        if (t + 2 < TT) {
            const size_t off = (size_t)(t + 2) * HIDD;
            rB_kq = (tid < 128) ? k[baseQK + off + lc] : q[baseQK + off + lc];
            if (tid < 64)       rB_vg = v[baseVA + off + half * 64 + tid];
            else if (tid < 128) rB_vg = a[baseVA + off + half * 64 + (tid - 64)];
            if (tid == 0)       rB_b = beta[(size_t)(b * TT + t + 2) * HH + h];
        }

        const float av = gsm[buf][vl];
        const float vt = vsm[buf][vl];
        const float bt = bsm[buf];

        uint64_t kf2[16], q2[16];
        #pragma unroll
        for (int j = 0; j < 8; j++)
            lds_v2u64(kf2[2 * j], kf2[2 * j + 1], kaddr[buf] + j * 16);
        #pragma unroll
        for (int j = 0; j < 8; j++)
            lds_v2u64(q2[2 * j], q2[2 * j + 1], qaddr[buf] + j * 16);

        // sk = S . k  (two chains to shorten dependency)
        uint64_t ska = 0ull, skb = 0ull;
        #pragma unroll
        for (int i = 0; i < 8; i++) {
            ska = f32x2_fma(s2[2 * i],     kf2[2 * i],     ska);
            skb = f32x2_fma(s2[2 * i + 1], kf2[2 * i + 1], skb);
        }
        float sk = unpack_sum(ska) + unpack_sum(skb);
        sk += __shfl_xor_sync(0xffffffffu, sk, 1);
        sk += __shfl_xor_sync(0xffffffffu, sk, 2);

        const float d  = bt * (sk - vt);
        const uint64_t dn2 = pack2(-d);
        const uint64_t av2 = pack2(av);

        uint64_t opa = 0ull, opb = 0ull;
        #pragma unroll
        for (int i = 0; i < 8; i++) {
            uint64_t n0 = f32x2_mul(dn2, kf2[2 * i]);
            uint64_t n1 = f32x2_mul(dn2, kf2[2 * i + 1]);
            s2[2 * i]     = f32x2_fma(av2, s2[2 * i],     n0);
            s2[2 * i + 1] = f32x2_fma(av2, s2[2 * i + 1], n1);
            opa = f32x2_fma(s2[2 * i],     q2[2 * i],     opa);
            opb = f32x2_fma(s2[2 * i + 1], q2[2 * i + 1], opb);
        }
        float op = unpack_sum(opa) + unpack_sum(opb);
        op += __shfl_xor_sync(0xffffffffu, op, 1);
        op += __shfl_xor_sync(0xffffffffu, op, 2);
        if (c == 0)
            o[(size_t)(b * TT + t) * HIDD + h * DKK + vg] = op;

        // stage t+1 from register set A (loaded 1-2 steps ago)
        if (t + 1 < TT) {
            const int nb = buf ^ 1;
            if (tid < 128) ksm[nb][lsm] = rA_kq;
            else           qsm[nb][lsm] = rA_kq;
            if (tid < 64)        vsm[nb][tid]      = rA_vg;
            else if (tid < 128)  gsm[nb][tid - 64] = rA_vg;
            if (tid == 0)        bsm[nb] = rA_b;
        }
        rA_kq = rB_kq; rA_vg = rB_vg; rA_b = rB_b;
    }
}

// ======================================================================
// LayerNorm over DV=128 + gate, output split to bf16 hi/lo (final GEMM A)
// ======================================================================
__global__ void ln_gate_kernel(const float* __restrict__ o, const float* __restrict__ g,
                               const float* __restrict__ lnw, const float* __restrict__ lnb,
                               __nv_bfloat16* __restrict__ ghi, __nv_bfloat16* __restrict__ glo)
{
    const int gw   = (int)(((size_t)blockIdx.x * blockDim.x + threadIdx.x) >> 5);
    const int lane = threadIdx.x & 31;
    const size_t base = (size_t)gw * 128 + lane * 4;
    float4 x = *(const float4*)(o + base);
    float s  = x.x + x.y + x.z + x.w;
    float ss = x.x * x.x + x.y * x.y + x.z * x.z + x.w * x.w;
    #pragma unroll
    for (int m = 16; m > 0; m >>= 1) {
        s  += __shfl_xor_sync(0xffffffffu, s,  m);
        ss += __shfl_xor_sync(0xffffffffu, ss, m);
    }
    const float mu  = s * (1.f / 128.f);
    const float var = ss * (1.f / 128.f) - mu * mu;
    const float inv = rsqrtf(var + EPS_F);
    const float4 wv = *(const float4*)(lnw + lane * 4);
    const float4 bv = *(const float4*)(lnb + lane * 4);
    const float4 gv = *(const float4*)(g + base);
    float r[4];
    r[0] = ((x.x - mu) * inv * wv.x + bv.x) * gv.x;
    r[1] = ((x.y - mu) * inv * wv.y + bv.y) * gv.y;
    r[2] = ((x.z - mu) * inv * wv.z + bv.z) * gv.z;
    r[3] = ((x.w - mu) * inv * wv.w + bv.w) * gv.w;
    __nv_bfloat16 h[4], l[4];
    #pragma unroll
    for (int i = 0; i < 4; i++) {
        h[i] = __float2bfloat16(r[i]);
        l[i] = __float2bfloat16(r[i] - __bfloat162float(h[i]));
    }
    *(__nv_bfloat162*)(ghi + base)     = __nv_bfloat162(h[0], h[1]);
    *(__nv_bfloat162*)(ghi + base + 2) = __nv_bfloat162(h[2], h[3]);
    *(__nv_bfloat162*)(glo + base)     = __nv_bfloat162(l[0], l[1]);
    *(__nv_bfloat162*)(glo + base + 2) = __nv_bfloat162(l[2], l[3]);
}

// ======================================================================
// launch
// ======================================================================
extern "C" void kernel_launch(void* const* d_in, const int* in_sizes, int n_in,
                              void* d_out, int out_size)
{
    const float* x       = (const float*)d_in[0];
    const float* Wq      = (const float*)d_in[1];
    const float* Wk      = (const float*)d_in[2];
    const float* Wv      = (const float*)d_in[3];
    const float* Wa      = (const float*)d_in[4];
    const float* ba      = (const float*)d_in[5];
    const float* Wb      = (const float*)d_in[6];
    const float* bb      = (const float*)d_in[7];
    const float* Wg      = (const float*)d_in[8];
    const float* Wo      = (const float*)d_in[9];
    const float* qconv_w = (const float*)d_in[10];
    const float* qconv_b = (const float*)d_in[11];
    const float* kconv_w = (const float*)d_in[12];
    const float* kconv_b = (const float*)d_in[13];
    const float* vconv_w = (const float*)d_in[14];
    const float* vconv_b = (const float*)d_in[15];
    const float* ln_w    = (const float*)d_in[16];
    const float* ln_b    = (const float*)d_in[17];

    void* sp = nullptr;
    cudaGetSymbolAddress(&sp, g_scratch);
    float* fb = (float*)sp;
    float* d_qpre = fb + 0 * BUFE;
    float* d_kpre = fb + 1 * BUFE;
    float* d_vpre = fb + 2 * BUFE;
    float* d_q    = fb + 3 * BUFE;
    float* d_k    = fb + 4 * BUFE;
    float* d_v    = fb + 5 * BUFE;
    float* d_a    = fb + 6 * BUFE;
    float* d_g    = fb + 7 * BUFE;
    float* d_o    = fb + 8 * BUFE;
    float* d_beta = fb + 9 * BUFE;

    void* bp = nullptr;
    cudaGetSymbolAddress(&bp, g_bf);
    __nv_bfloat16* hb = (__nv_bfloat16*)bp;
    __nv_bfloat16* xhi = hb + 0 * BUFE;
    __nv_bfloat16* xlo = hb + 1 * BUFE;
    __nv_bfloat16* ghi = hb + 2 * BUFE;
    __nv_bfloat16* glo = hb + 3 * BUFE;
    __nv_bfloat16* wt  = hb + 4 * BUFE;       // 12 x WE: (hi,lo) x {q,k,v,a,g,o}
    __nv_bfloat16* Wq_hi = wt + 0 * WE, *Wq_lo = wt + 1 * WE;
    __nv_bfloat16* Wk_hi = wt + 2 * WE, *Wk_lo = wt + 3 * WE;
    __nv_bfloat16* Wv_hi = wt + 4 * WE, *Wv_lo = wt + 5 * WE;
    __nv_bfloat16* Wa_hi = wt + 6 * WE, *Wa_lo = wt + 7 * WE;
    __nv_bfloat16* Wg_hi = wt + 8 * WE, *Wg_lo = wt + 9 * WE;
    __nv_bfloat16* Wo_hi = wt + 10 * WE, *Wo_lo = wt + 11 * WE;

    cudaFuncSetAttribute(gemm_bf16x3_kernel,
                         cudaFuncAttributeMaxDynamicSharedMemorySize, SMEM_GEMM);

    // (1) split x
    split_kernel<<<(int)(BUFE / 4 / 256), 256>>>(x, xhi, xlo);

    // (2) all weight transposes
    WSet ws;
    ws.src[0] = Wq; ws.hi[0] = Wq_hi; ws.lo[0] = Wq_lo;
    ws.src[1] = Wk; ws.hi[1] = Wk_hi; ws.lo[1] = Wk_lo;
    ws.src[2] = Wv; ws.hi[2] = Wv_hi; ws.lo[2] = Wv_lo;
    ws.src[3] = Wa; ws.hi[3] = Wa_hi; ws.lo[3] = Wa_lo;
    ws.src[4] = Wg; ws.hi[4] = Wg_hi; ws.lo[4] = Wg_lo;
    ws.src[5] = Wo; ws.hi[5] = Wo_hi; ws.lo[5] = Wo_lo;
    transpose_split_all_kernel<<<dim3(HIDD / 32, HIDD / 32, 6), dim3(32, 8)>>>(ws);

    // (3) beta
    beta_kernel<<<NBT / 16, 256>>>(x, Wb, bb, d_beta);

    // (4) 5 projections, one batched launch
    GemmBatch gb;
    gb.bh[0] = Wq_hi; gb.bl[0] = Wq_lo; gb.bias[0] = nullptr; gb.C[0] = d_qpre; gb.epi[0] = 0;
    gb.bh[1] = Wk_hi; gb.bl[1] = Wk_lo; gb.bias[1] = nullptr; gb.C[1] = d_kpre; gb.epi[1] = 0;
    gb.bh[2] = Wv_hi; gb.bl[2] = Wv_lo; gb.bias[2] = nullptr; gb.C[2] = d_vpre; gb.epi[2] = 0;
    gb.bh[3] = Wa_hi; gb.bl[3] = Wa_lo; gb.bias[3] = ba;      gb.C[3] = d_a;    gb.epi[3] = 1;
    gb.bh[4] = Wg_hi; gb.bl[4] = Wg_lo; gb.bias[4] = nullptr; gb.C[4] = d_g;    gb.epi[4] = 1;
    gemm_bf16x3_kernel<<<dim3(HIDD / 128, NBT / 128, 5), 256, SMEM_GEMM>>>(xhi, xlo, gb);

    // (5) 3 convs, one batched launch
    ConvSet cs;
    cs.u[0] = d_qpre; cs.w[0] = qconv_w; cs.b[0] = qconv_b; cs.y[0] = d_q; cs.scale[0] = 1.f;
    cs.u[1] = d_kpre; cs.w[1] = kconv_w; cs.b[1] = kconv_b; cs.y[1] = d_k; cs.scale[1] = SCALE_F;
    cs.u[2] = d_vpre; cs.w[2] = vconv_w; cs.b[2] = vconv_b; cs.y[2] = d_v; cs.scale[2] = 1.f;
    conv_silu_all_kernel<<<dim3((int)((size_t)NBT * HIDD / 4 / 256), 1, 3), 256>>>(cs);

    // (6) scan  <- profiled by ncu (-s 5 -c 1)
    scan_kernel<<<BB * HH * 2, 256>>>(d_q, d_k, d_v, d_a, d_beta, d_o);

    // (7) LN + gate
    ln_gate_kernel<<<(NBT * HH) / 8, 256>>>(d_o, d_g, ln_w, ln_b, ghi, glo);

    // (8) output GEMM
    GemmBatch gbo;
    gbo.bh[0] = Wo_hi; gbo.bl[0] = Wo_lo; gbo.bias[0] = nullptr; gbo.C[0] = (float*)d_out; gbo.epi[0] = 0;
    #pragma unroll
    for (int i = 1; i < 5; i++) { gbo.bh[i] = Wo_hi; gbo.bl[i] = Wo_lo; gbo.bias[i] = nullptr; gbo.C[i] = (float*)d_out; gbo.epi[i] = 0; }
    gemm_bf16x3_kernel<<<dim3(HIDD / 128, NBT / 128, 1), 256, SMEM_GEMM>>>(ghi, glo, gbo);

    (void)in_sizes; (void)n_in; (void)out_size;
}

// round 9
// speedup vs baseline: 1.4323x; 1.0150x over previous
#include <cuda_runtime.h>
#include <cuda_bf16.h>
#include <cstdint>
#include <cstddef>

// ---------------- problem constants ----------------
#define BB   4
#define TT   2048
#define HIDD 2048
#define HH   16
#define DKK  128
#define DVV  128
#define NBT  (BB*TT)           // 8192 rows
static constexpr float SCALE_F = 0.08838834764831845f;  // 128^-0.5
static constexpr float EPS_F   = 1e-5f;

// ---------------- scratch (device globals; no allocation allowed) ----------------
#define BUFE ((size_t)NBT * HIDD)      // 16.78M elems
#define WE   ((size_t)HIDD * HIDD)     // 4.19M elems
__device__ float         g_scratch[BUFE * 9 + (size_t)NBT * HH];
__device__ __nv_bfloat16 g_bf[BUFE * 4 + WE * 12];

__device__ __forceinline__ float sigmoidf_(float x) { return 1.f / (1.f + expf(-x)); }

__device__ __forceinline__ uint32_t smem_u32(const void* p) {
    uint32_t a;
    asm("{ .reg .u64 t; cvta.to.shared.u64 t, %1; cvt.u32.u64 %0, t; }" : "=r"(a) : "l"(p));
    return a;
}
__device__ __forceinline__ void cp16(uint32_t dst, const void* src) {
    asm volatile("cp.async.cg.shared.global [%0], [%1], 16;" :: "r"(dst), "l"(src));
}
__device__ __forceinline__ void cp_commit() {
    asm volatile("cp.async.commit_group;" ::: "memory");
}
__device__ __forceinline__ void ldsm4(uint32_t* r, uint32_t addr) {
    asm volatile("ldmatrix.sync.aligned.m8n8.x4.shared.b16 {%0,%1,%2,%3}, [%4];"
                 : "=r"(r[0]), "=r"(r[1]), "=r"(r[2]), "=r"(r[3]) : "r"(addr));
}
__device__ __forceinline__ void mma16816(float* c, const uint32_t* a, uint32_t b0, uint32_t b1) {
    asm volatile("mma.sync.aligned.m16n8k16.row.col.f32.bf16.bf16.f32 "
                 "{%0,%1,%2,%3}, {%4,%5,%6,%7}, {%8,%9}, {%0,%1,%2,%3};"
                 : "+f"(c[0]), "+f"(c[1]), "+f"(c[2]), "+f"(c[3])
                 : "r"(a[0]), "r"(a[1]), "r"(a[2]), "r"(a[3]), "r"(b0), "r"(b1));
}

// ---- packed f32x2 helpers ----
__device__ __forceinline__ uint64_t f32x2_fma(uint64_t a, uint64_t b, uint64_t c) {
    uint64_t d;
    asm("fma.rn.f32x2 %0, %1, %2, %3;" : "=l"(d) : "l"(a), "l"(b), "l"(c));
    return d;
}
__device__ __forceinline__ uint64_t f32x2_mul(uint64_t a, uint64_t b) {
    uint64_t d;
    asm("mul.rn.f32x2 %0, %1, %2;" : "=l"(d) : "l"(a), "l"(b));
    return d;
}
__device__ __forceinline__ uint64_t pack2(float x) {
    uint64_t d; uint32_t u = __float_as_uint(x);
    asm("mov.b64 %0, {%1, %1};" : "=l"(d) : "r"(u));
    return d;
}
__device__ __forceinline__ float unpack_sum(uint64_t p) {
    uint32_t lo, hi;
    asm("mov.b64 {%0, %1}, %2;" : "=r"(lo), "=r"(hi) : "l"(p));
    return __uint_as_float(lo) + __uint_as_float(hi);
}
__device__ __forceinline__ void lds_v2u64(uint64_t& a, uint64_t& b, uint32_t addr) {
    asm volatile("ld.shared.v2.u64 {%0, %1}, [%2];" : "=l"(a), "=l"(b) : "r"(addr));
}

// ======================================================================
// mma.sync GEMM, bf16x3 split, batched over z (up to 5 weights, shared A).
// CTA tile 128x128, BK=32, 3-stage cp.async, 2 CTAs/SM.
// Addressing folded to per-thread constants + immediates:
//   loader: seg=(tid&7) const across i, rows differ by 32*i -> smem +4096*i,
//           global +32*GK*i (immediates); swizzle XOR is per-thread const.
//   compute: 4 hoisted koff^xor values; mt/nt offsets are +2048 immediates.
// ======================================================================
#define GK     2048
#define BK     32
#define NCH    (GK / BK)          // 64
#define SM_A   0
#define SM_B   (16 * 1024)
#define STAGE  (32 * 1024)
#define NSTAGE 3
#define SMEM_GEMM (NSTAGE * STAGE)     // 98304

struct GemmBatch {
    const __nv_bfloat16* bh[5];
    const __nv_bfloat16* bl[5];
    const float* bias[5];
    float* C[5];
    int epi[5];
};

__global__ void __launch_bounds__(256, 2)
gemm_bf16x3_kernel(const __nv_bfloat16* __restrict__ Ahi, const __nv_bfloat16* __restrict__ Alo,
                   GemmBatch gb)
{
    extern __shared__ __align__(1024) char sm[];
    const uint32_t smb = smem_u32(sm);

    const int z    = blockIdx.z;
    const int tid  = threadIdx.x;
    const int wid  = tid >> 5;
    const int lane = tid & 31;
    const int bm   = blockIdx.y * 128;
    const int bn   = blockIdx.x * 128;
    const int wm   = wid & 3;       // M group (4 x 32 rows)
    const int wn   = wid >> 2;      // N group (2 x 64 cols)

    // ---- loader constants (all per-thread invariant) ----
    const int lrow = tid >> 3;          // 0..31  (rows lrow + 32*i)
    const int lseg = tid & 7;           // constant across i
    const uint32_t swz = (uint32_t)((lseg * 16) ^ ((lrow & 7) << 4));
    const uint32_t sw0 = (uint32_t)(lrow * 128) + swz;   // smem offset for i=0
    const size_t   gofs = (size_t)lrow * GK + (lseg & 3) * 8;

    const __nv_bfloat16* Aptr = ((lseg < 4) ? Ahi : Alo) + (size_t)bm * GK + gofs;
    const __nv_bfloat16* Bptr = ((lseg < 4) ? gb.bh[z] : gb.bl[z]) + (size_t)bn * GK + gofs;

    const float* bias = gb.bias[z];
    float* C = gb.C[z];
    const int epi = gb.epi[z];

    uint32_t psbase = smb;     // prefetch slot base (slot 0 first)
    auto prefetch = [&]() {
        const uint32_t pa = psbase + SM_A + sw0;
        const uint32_t pb = psbase + SM_B + sw0;
        #pragma unroll
        for (int i = 0; i < 4; i++) {
            cp16(pa + i * 4096, Aptr + (size_t)i * 32 * GK);
            cp16(pb + i * 4096, Bptr + (size_t)i * 32 * GK);
        }
        cp_commit();
        Aptr += BK;  Bptr += BK;
        psbase += STAGE;
        if (psbase == smb + NSTAGE * STAGE) psbase = smb;
    };

    prefetch();     // chunk 0 -> slot 0
    prefetch();     // chunk 1 -> slot 1

    float acc[2][8][4];
    #pragma unroll
    for (int i = 0; i < 2; i++)
        #pragma unroll
        for (int j = 0; j < 8; j++)
            #pragma unroll
            for (int q = 0; q < 4; q++) acc[i][j][q] = 0.f;

    // ---- compute-phase constants ----
    const int l16  = lane & 15;
    const uint32_t xorv  = (uint32_t)((lane & 7) << 4);
    const uint32_t chalf = (uint32_t)((lane >> 4) * 16);
    const uint32_t xh0 = (chalf)      ^ xorv;   // kk=0, hi half (bytes 0..63)
    const uint32_t xh1 = (32 + chalf) ^ xorv;   // kk=1, hi
    const uint32_t xl0 = (64 + chalf) ^ xorv;   // kk=0, lo half (bytes 64..127)
    const uint32_t xl1 = (96 + chalf) ^ xorv;   // kk=1, lo
    const uint32_t aBase = SM_A + (uint32_t)((wm * 32 + l16) << 7);
    const uint32_t bBase = SM_B + (uint32_t)((wn * 64 + l16) << 7);

    uint32_t sbase = smb;
    for (int c = 0; c < NCH; c++) {
        if (c + 1 < NCH) asm volatile("cp.async.wait_group 1;" ::: "memory");
        else             asm volatile("cp.async.wait_group 0;" ::: "memory");
        __syncthreads();
        if (c + 2 < NCH) prefetch();

        const uint32_t sA = sbase + aBase;
        const uint32_t sB = sbase + bBase;
        #pragma unroll
        for (int kk = 0; kk < 2; kk++) {
            const uint32_t xh = kk ? xh1 : xh0;
            const uint32_t xl = kk ? xl1 : xl0;
            const uint32_t sAh = sA + xh, sAl = sA + xl;
            const uint32_t sBh = sB + xh, sBl = sB + xl;
            uint32_t ah[2][4], al[2][4];
            ldsm4(ah[0], sAh);
            ldsm4(ah[1], sAh + 2048);
            ldsm4(al[0], sAl);
            ldsm4(al[1], sAl + 2048);
            #pragma unroll
            for (int nt = 0; nt < 4; nt++) {
                uint32_t bh4[4], bl4[4];
                ldsm4(bh4, sBh + nt * 2048);
                ldsm4(bl4, sBl + nt * 2048);
                #pragma unroll
                for (int mt = 0; mt < 2; mt++) {
                    mma16816(acc[mt][nt * 2],     ah[mt], bh4[0], bh4[2]);
                    mma16816(acc[mt][nt * 2 + 1], ah[mt], bh4[1], bh4[3]);
                    mma16816(acc[mt][nt * 2],     al[mt], bh4[0], bh4[2]);
                    mma16816(acc[mt][nt * 2 + 1], al[mt], bh4[1], bh4[3]);
                    mma16816(acc[mt][nt * 2],     ah[mt], bl4[0], bl4[2]);
                    mma16816(acc[mt][nt * 2 + 1], ah[mt], bl4[1], bl4[3]);
                }
            }
        }
        sbase += STAGE;
        if (sbase == smb + NSTAGE * STAGE) sbase = smb;
    }

    // epilogue
    #pragma unroll
    for (int mt = 0; mt < 2; mt++) {
        const int r0 = bm + wm * 32 + mt * 16 + (lane >> 2);
        #pragma unroll
        for (int j = 0; j < 8; j++) {
            const int cc = bn + wn * 64 + j * 8 + (lane & 3) * 2;
            float v0 = acc[mt][j][0], v1 = acc[mt][j][1];
            float v2 = acc[mt][j][2], v3 = acc[mt][j][3];
            if (epi == 1) {
                const float b0 = bias ? bias[cc]     : 0.f;
                const float b1 = bias ? bias[cc + 1] : 0.f;
                v0 = sigmoidf_(v0 + b0); v1 = sigmoidf_(v1 + b1);
                v2 = sigmoidf_(v2 + b0); v3 = sigmoidf_(v3 + b1);
            }
            *(float2*)(C + (size_t)r0 * HIDD + cc)       = make_float2(v0, v1);
            *(float2*)(C + (size_t)(r0 + 8) * HIDD + cc) = make_float2(v2, v3);
        }
    }
}

// ======================================================================
// elementwise fp32 -> (bf16 hi, bf16 lo), 4 elems/thread
// ======================================================================
__global__ void split_kernel(const float* __restrict__ in,
                             __nv_bfloat16* __restrict__ hi, __nv_bfloat16* __restrict__ lo)
{
    const size_t i = ((size_t)blockIdx.x * blockDim.x + threadIdx.x) * 4;
    const float4 v = *(const float4*)(in + i);
    __nv_bfloat16 h[4], l[4];
    const float* vp = (const float*)&v;
    #pragma unroll
    for (int j = 0; j < 4; j++) {
        h[j] = __float2bfloat16(vp[j]);
        l[j] = __float2bfloat16(vp[j] - __bfloat162float(h[j]));
    }
    *(__nv_bfloat162*)(hi + i)     = __nv_bfloat162(h[0], h[1]);
    *(__nv_bfloat162*)(hi + i + 2) = __nv_bfloat162(h[2], h[3]);
    *(__nv_bfloat162*)(lo + i)     = __nv_bfloat162(l[0], l[1]);
    *(__nv_bfloat162*)(lo + i + 2) = __nv_bfloat162(l[2], l[3]);
}

// ======================================================================
// all six W [K=2048, N=2048] f32 -> W^T hi/lo [N, K] bf16 in ONE launch
// ======================================================================
struct WSet {
    const float* src[6];
    __nv_bfloat16* hi[6];
    __nv_bfloat16* lo[6];
};
__global__ void transpose_split_all_kernel(WSet ws)
{
    __shared__ float tile[32][33];
    const int z  = blockIdx.z;
    const float* W = ws.src[z];
    __nv_bfloat16* hi = ws.hi[z];
    __nv_bfloat16* lo = ws.lo[z];
    const int tx = threadIdx.x, ty = threadIdx.y;     // (32, 8)
    const int x0 = blockIdx.x * 32, y0 = blockIdx.y * 32;
    #pragma unroll
    for (int j = 0; j < 32; j += 8)
        tile[ty + j][tx] = W[(size_t)(y0 + ty + j) * HIDD + x0 + tx];
    __syncthreads();
    #pragma unroll
    for (int j = 0; j < 32; j += 8) {
        const float v = tile[tx][ty + j];
        const __nv_bfloat16 h = __float2bfloat16(v);
        const size_t o = (size_t)(x0 + ty + j) * HIDD + y0 + tx;
        hi[o] = h;
        lo[o] = __float2bfloat16(v - __bfloat162float(h));
    }
}

// ======================================================================
// beta = sigmoid(x @ Wb + bb)
// ======================================================================
__global__ void beta_kernel(const float* __restrict__ x, const float* __restrict__ Wb,
                            const float* __restrict__ bb, float* __restrict__ out)
{
    const int row = blockIdx.x * 16 + (threadIdx.x >> 4);
    const int col = threadIdx.x & 15;
    const float* xr = x + (size_t)row * HIDD;
    float acc = 0.f;
    for (int k = 0; k < HIDD; k += 4) {
        float4 xv = *(const float4*)(xr + k);
        acc += xv.x * Wb[(k + 0) * HH + col];
        acc += xv.y * Wb[(k + 1) * HH + col];
        acc += xv.z * Wb[(k + 2) * HH + col];
        acc += xv.w * Wb[(k + 3) * HH + col];
    }
    out[(size_t)row * HH + col] = sigmoidf_(acc + bb[col]);
}

// ======================================================================
// 3 causal depthwise convs (K=4) + bias + SiLU (+scale) in one launch,
// 4 channels per thread (float4)
// ======================================================================
struct ConvSet {
    const float* u[3];
    const float* w[3];
    const float* b[3];
    float* y[3];
    float scale[3];
};
__global__ void conv_silu_all_kernel(ConvSet cs)
{
    const int z = blockIdx.z;
    const size_t e = ((size_t)blockIdx.x * blockDim.x + threadIdx.x) * 4;
    const int c = (int)(e & (HIDD - 1));
    const int t = (int)((e >> 11) & (TT - 1));
    const float* u = cs.u[z];
    const float* w = cs.w[z];
    float4 acc = *(const float4*)(cs.b[z] + c);
    const float4 w0 = *(const float4*)(w + (size_t)c * 4);
    const float4 w1 = *(const float4*)(w + (size_t)(c + 1) * 4);
    const float4 w2 = *(const float4*)(w + (size_t)(c + 2) * 4);
    const float4 w3 = *(const float4*)(w + (size_t)(c + 3) * 4);
    const float* w0p = (const float*)&w0;
    const float* w1p = (const float*)&w1;
    const float* w2p = (const float*)&w2;
    const float* w3p = (const float*)&w3;
    #pragma unroll
    for (int j = 0; j < 4; j++) {
        if (t - 3 + j >= 0) {
            const float4 u4 = *(const float4*)(u + e + (ptrdiff_t)(j - 3) * HIDD);
            acc.x += w0p[j] * u4.x;
            acc.y += w1p[j] * u4.y;
            acc.z += w2p[j] * u4.z;
            acc.w += w3p[j] * u4.w;
        }
    }
    const float s = cs.scale[z];
    acc.x = acc.x * sigmoidf_(acc.x) * s;
    acc.y = acc.y * sigmoidf_(acc.y) * s;
    acc.z = acc.z * sigmoidf_(acc.z) * s;
    acc.w = acc.w * sigmoidf_(acc.w) * s;
    *(float4*)(cs.y[z] + e) = acc;
}

// ======================================================================
// Delta-rule scan: f32x2 math + two-step-ahead register prefetch.
// 128 blocks x 256 threads; thread = (v in 0..63, 32-k chunk as 16 f32x2).
// ======================================================================
__global__ void __launch_bounds__(256, 1) scan_kernel(
    const float* __restrict__ q, const float* __restrict__ k,
    const float* __restrict__ v, const float* __restrict__ a,
    const float* __restrict__ beta, float* __restrict__ o)
{
    __shared__ __align__(16) float ksm[2][4 * 36];
    __shared__ __align__(16) float qsm[2][4 * 36];
    __shared__ float vsm[2][64];
    __shared__ float gsm[2][64];
    __shared__ float bsm[2];

    const int blk  = blockIdx.x;
    const int b    = blk >> 5;
    const int h    = (blk >> 1) & 15;
    const int half = blk & 1;

    const int tid = threadIdx.x;
    const int vl  = tid >> 2;
    const int c   = tid & 3;
    const int vg  = half * 64 + vl;

    const int lc  = tid & 127;
    const int lsm = (lc >> 5) * 36 + (lc & 31);

    const size_t baseQK = (size_t)b * TT * HIDD + h * DKK;
    const size_t baseVA = (size_t)b * TT * HIDD + h * DVV;

    uint64_t s2[16];
    #pragma unroll
    for (int i = 0; i < 16; i++) s2[i] = 0ull;

    uint32_t kaddr[2], qaddr[2];
    #pragma unroll
    for (int bb2 = 0; bb2 < 2; bb2++) {
        kaddr[bb2] = smem_u32(&ksm[bb2][c * 36]);
        qaddr[bb2] = smem_u32(&qsm[bb2][c * 36]);
    }

    if (tid < 128) ksm[0][lsm] = k[baseQK + lc];
    else           qsm[0][lsm] = q[baseQK + lc];
    if (tid < 64)            vsm[0][tid]      = v[baseVA + half * 64 + tid];
    else if (tid < 128)      gsm[0][tid - 64] = a[baseVA + half * 64 + (tid - 64)];
    if (tid == 0)            bsm[0] = beta[(size_t)b * TT * HH + h];

    float rA_kq = 0.f, rA_vg = 0.f, rA_b = 0.f;
    {
        const size_t off = (size_t)1 * HIDD;
        rA_kq = (tid < 128) ? k[baseQK + off + lc] : q[baseQK + off + lc];
        if (tid < 64)       rA_vg = v[baseVA + off + half * 64 + tid];
        else if (tid < 128) rA_vg = a[baseVA + off + half * 64 + (tid - 64)];
        if (tid == 0)       rA_b = beta[(size_t)(b * TT + 1) * HH + h];
    }

    for (int t = 0; t < TT; t++) {
        const int buf = t & 1;
        __syncthreads();

        float rB_kq = 0.f, rB_vg = 0.f, rB_b = 0.f;
        if (t + 2 < TT) {
            const size_t off = (size_t)(t + 2) * HIDD;
            rB_kq = (tid < 128) ? k[baseQK + off + lc] : q[baseQK + off + lc];
            if (tid < 64)       rB_vg = v[baseVA + off + half * 64 + tid];
            else if (tid < 128) rB_vg = a[baseVA + off + half * 64 + (tid - 64)];
            if (tid == 0)       rB_b = beta[(size_t)(b * TT + t + 2) * HH + h];
        }

        const float av = gsm[buf][vl];
        const float vt = vsm[buf][vl];
        const float bt = bsm[buf];

        uint64_t kf2[16], q2[16];
        #pragma unroll
        for (int j = 0; j < 8; j++)
            lds_v2u64(kf2[2 * j], kf2[2 * j + 1], kaddr[buf] + j * 16);
        #pragma unroll
        for (int j = 0; j < 8; j++)
            lds_v2u64(q2[2 * j], q2[2 * j + 1], qaddr[buf] + j * 16);

        uint64_t ska = 0ull, skb = 0ull;
        #pragma unroll
        for (int i = 0; i < 8; i++) {
            ska = f32x2_fma(s2[2 * i],     kf2[2 * i],     ska);
            skb = f32x2_fma(s2[2 * i + 1], kf2[2 * i + 1], skb);
        }
        float sk = unpack_sum(ska) + unpack_sum(skb);
        sk += __shfl_xor_sync(0xffffffffu, sk, 1);
        sk += __shfl_xor_sync(0xffffffffu, sk, 2);

        const float d  = bt * (sk - vt);
        const uint64_t dn2 = pack2(-d);
        const uint64_t av2 = pack2(av);

        uint64_t opa = 0ull, opb = 0ull;
        #pragma unroll
        for (int i = 0; i < 8; i++) {
            uint64_t n0 = f32x2_mul(dn2, kf2[2 * i]);
            uint64_t n1 = f32x2_mul(dn2, kf2[2 * i + 1]);
            s2[2 * i]     = f32x2_fma(av2, s2[2 * i],     n0);
            s2[2 * i + 1] = f32x2_fma(av2, s2[2 * i + 1], n1);
            opa = f32x2_fma(s2[2 * i],     q2[2 * i],     opa);
            opb = f32x2_fma(s2[2 * i + 1], q2[2 * i + 1], opb);
        }
        float op = unpack_sum(opa) + unpack_sum(opb);
        op += __shfl_xor_sync(0xffffffffu, op, 1);
        op += __shfl_xor_sync(0xffffffffu, op, 2);
        if (c == 0)
            o[(size_t)(b * TT + t) * HIDD + h * DKK + vg] = op;

        if (t + 1 < TT) {
            const int nb = buf ^ 1;
            if (tid < 128) ksm[nb][lsm] = rA_kq;
            else           qsm[nb][lsm] = rA_kq;
            if (tid < 64)        vsm[nb][tid]      = rA_vg;
            else if (tid < 128)  gsm[nb][tid - 64] = rA_vg;
            if (tid == 0)        bsm[nb] = rA_b;
        }
        rA_kq = rB_kq; rA_vg = rB_vg; rA_b = rB_b;
    }
}

// ======================================================================
// LayerNorm over DV=128 + gate, output split to bf16 hi/lo (final GEMM A)
// ======================================================================
__global__ void ln_gate_kernel(const float* __restrict__ o, const float* __restrict__ g,
                               const float* __restrict__ lnw, const float* __restrict__ lnb,
                               __nv_bfloat16* __restrict__ ghi, __nv_bfloat16* __restrict__ glo)
{
    const int gw   = (int)(((size_t)blockIdx.x * blockDim.x + threadIdx.x) >> 5);
    const int lane = threadIdx.x & 31;
    const size_t base = (size_t)gw * 128 + lane * 4;
    float4 x = *(const float4*)(o + base);
    float s  = x.x + x.y + x.z + x.w;
    float ss = x.x * x.x + x.y * x.y + x.z * x.z + x.w * x.w;
    #pragma unroll
    for (int m = 16; m > 0; m >>= 1) {
        s  += __shfl_xor_sync(0xffffffffu, s,  m);
        ss += __shfl_xor_sync(0xffffffffu, ss, m);
    }
    const float mu  = s * (1.f / 128.f);
    const float var = ss * (1.f / 128.f) - mu * mu;
    const float inv = rsqrtf(var + EPS_F);
    const float4 wv = *(const float4*)(lnw + lane * 4);
    const float4 bv = *(const float4*)(lnb + lane * 4);
    const float4 gv = *(const float4*)(g + base);
    float r[4];
    r[0] = ((x.x - mu) * inv * wv.x + bv.x) * gv.x;
    r[1] = ((x.y - mu) * inv * wv.y + bv.y) * gv.y;
    r[2] = ((x.z - mu) * inv * wv.z + bv.z) * gv.z;
    r[3] = ((x.w - mu) * inv * wv.w + bv.w) * gv.w;
    __nv_bfloat16 h[4], l[4];
    #pragma unroll
    for (int i = 0; i < 4; i++) {
        h[i] = __float2bfloat16(r[i]);
        l[i] = __float2bfloat16(r[i] - __bfloat162float(h[i]));
    }
    *(__nv_bfloat162*)(ghi + base)     = __nv_bfloat162(h[0], h[1]);
    *(__nv_bfloat162*)(ghi + base + 2) = __nv_bfloat162(h[2], h[3]);
    *(__nv_bfloat162*)(glo + base)     = __nv_bfloat162(l[0], l[1]);
    *(__nv_bfloat162*)(glo + base + 2) = __nv_bfloat162(l[2], l[3]);
}

// ======================================================================
// launch
// ======================================================================
extern "C" void kernel_launch(void* const* d_in, const int* in_sizes, int n_in,
                              void* d_out, int out_size)
{
    const float* x       = (const float*)d_in[0];
    const float* Wq      = (const float*)d_in[1];
    const float* Wk      = (const float*)d_in[2];
    const float* Wv      = (const float*)d_in[3];
    const float* Wa      = (const float*)d_in[4];
    const float* ba      = (const float*)d_in[5];
    const float* Wb      = (const float*)d_in[6];
    const float* bb      = (const float*)d_in[7];
    const float* Wg      = (const float*)d_in[8];
    const float* Wo      = (const float*)d_in[9];
    const float* qconv_w = (const float*)d_in[10];
    const float* qconv_b = (const float*)d_in[11];
    const float* kconv_w = (const float*)d_in[12];
    const float* kconv_b = (const float*)d_in[13];
    const float* vconv_w = (const float*)d_in[14];
    const float* vconv_b = (const float*)d_in[15];
    const float* ln_w    = (const float*)d_in[16];
    const float* ln_b    = (const float*)d_in[17];

    void* sp = nullptr;
    cudaGetSymbolAddress(&sp, g_scratch);
    float* fb = (float*)sp;
    float* d_qpre = fb + 0 * BUFE;
    float* d_kpre = fb + 1 * BUFE;
    float* d_vpre = fb + 2 * BUFE;
    float* d_q    = fb + 3 * BUFE;
    float* d_k    = fb + 4 * BUFE;
    float* d_v    = fb + 5 * BUFE;
    float* d_a    = fb + 6 * BUFE;
    float* d_g    = fb + 7 * BUFE;
    float* d_o    = fb + 8 * BUFE;
    float* d_beta = fb + 9 * BUFE;

    void* bp = nullptr;
    cudaGetSymbolAddress(&bp, g_bf);
    __nv_bfloat16* hb = (__nv_bfloat16*)bp;
    __nv_bfloat16* xhi = hb + 0 * BUFE;
    __nv_bfloat16* xlo = hb + 1 * BUFE;
    __nv_bfloat16* ghi = hb + 2 * BUFE;
    __nv_bfloat16* glo = hb + 3 * BUFE;
    __nv_bfloat16* wt  = hb + 4 * BUFE;       // 12 x WE: (hi,lo) x {q,k,v,a,g,o}
    __nv_bfloat16* Wq_hi = wt + 0 * WE, *Wq_lo = wt + 1 * WE;
    __nv_bfloat16* Wk_hi = wt + 2 * WE, *Wk_lo = wt + 3 * WE;
    __nv_bfloat16* Wv_hi = wt + 4 * WE, *Wv_lo = wt + 5 * WE;
    __nv_bfloat16* Wa_hi = wt + 6 * WE, *Wa_lo = wt + 7 * WE;
    __nv_bfloat16* Wg_hi = wt + 8 * WE, *Wg_lo = wt + 9 * WE;
    __nv_bfloat16* Wo_hi = wt + 10 * WE, *Wo_lo = wt + 11 * WE;

    cudaFuncSetAttribute(gemm_bf16x3_kernel,
                         cudaFuncAttributeMaxDynamicSharedMemorySize, SMEM_GEMM);

    // (1) split x
    split_kernel<<<(int)(BUFE / 4 / 256), 256>>>(x, xhi, xlo);

    // (2) all weight transposes
    WSet ws;
    ws.src[0] = Wq; ws.hi[0] = Wq_hi; ws.lo[0] = Wq_lo;
    ws.src[1] = Wk; ws.hi[1] = Wk_hi; ws.lo[1] = Wk_lo;
    ws.src[2] = Wv; ws.hi[2] = Wv_hi; ws.lo[2] = Wv_lo;
    ws.src[3] = Wa; ws.hi[3] = Wa_hi; ws.lo[3] = Wa_lo;
    ws.src[4] = Wg; ws.hi[4] = Wg_hi; ws.lo[4] = Wg_lo;
    ws.src[5] = Wo; ws.hi[5] = Wo_hi; ws.lo[5] = Wo_lo;
    transpose_split_all_kernel<<<dim3(HIDD / 32, HIDD / 32, 6), dim3(32, 8)>>>(ws);

    // (3) beta
    beta_kernel<<<NBT / 16, 256>>>(x, Wb, bb, d_beta);

    // (4) 5 projections, one batched launch
    GemmBatch gb;
    gb.bh[0] = Wq_hi; gb.bl[0] = Wq_lo; gb.bias[0] = nullptr; gb.C[0] = d_qpre; gb.epi[0] = 0;
    gb.bh[1] = Wk_hi; gb.bl[1] = Wk_lo; gb.bias[1] = nullptr; gb.C[1] = d_kpre; gb.epi[1] = 0;
    gb.bh[2] = Wv_hi; gb.bl[2] = Wv_lo; gb.bias[2] = nullptr; gb.C[2] = d_vpre; gb.epi[2] = 0;
    gb.bh[3] = Wa_hi; gb.bl[3] = Wa_lo; gb.bias[3] = ba;      gb.C[3] = d_a;    gb.epi[3] = 1;
    gb.bh[4] = Wg_hi; gb.bl[4] = Wg_lo; gb.bias[4] = nullptr; gb.C[4] = d_g;    gb.epi[4] = 1;
    gemm_bf16x3_kernel<<<dim3(HIDD / 128, NBT / 128, 5), 256, SMEM_GEMM>>>(xhi, xlo, gb);

    // (5) 3 convs, one batched launch
    ConvSet cs;
    cs.u[0] = d_qpre; cs.w[0] = qconv_w; cs.b[0] = qconv_b; cs.y[0] = d_q; cs.scale[0] = 1.f;
    cs.u[1] = d_kpre; cs.w[1] = kconv_w; cs.b[1] = kconv_b; cs.y[1] = d_k; cs.scale[1] = SCALE_F;
    cs.u[2] = d_vpre; cs.w[2] = vconv_w; cs.b[2] = vconv_b; cs.y[2] = d_v; cs.scale[2] = 1.f;
    conv_silu_all_kernel<<<dim3((int)((size_t)NBT * HIDD / 4 / 256), 1, 3), 256>>>(cs);

    // (6) scan
    scan_kernel<<<BB * HH * 2, 256>>>(d_q, d_k, d_v, d_a, d_beta, d_o);

    // (7) LN + gate
    ln_gate_kernel<<<(NBT * HH) / 8, 256>>>(d_o, d_g, ln_w, ln_b, ghi, glo);

    // (8) output GEMM
    GemmBatch gbo = {};
    gbo.bh[0] = Wo_hi; gbo.bl[0] = Wo_lo; gbo.bias[0] = nullptr;
    gbo.C[0] = (float*)d_out; gbo.epi[0] = 0;
    gemm_bf16x3_kernel<<<dim3(HIDD / 128, NBT / 128, 1), 256, SMEM_GEMM>>>(ghi, glo, gbo);

    (void)in_sizes; (void)n_in; (void)out_size;
}

// round 13
// speedup vs baseline: 1.7534x; 1.2242x over previous
#include <cuda_runtime.h>
#include <cuda_fp16.h>
#include <cstdint>
#include <cstddef>

// ---------------- problem constants ----------------
#define BB   4
#define TT   2048
#define HIDD 2048
#define HH   16
#define DKK  128
#define DVV  128
#define NBT  (BB*TT)           // 8192 rows
static constexpr float SCALE_F = 0.08838834764831845f;  // 128^-0.5
static constexpr float EPS_F   = 1e-5f;

// ---------------- scratch (device globals; no allocation allowed) ----------------
#define BUFE ((size_t)NBT * HIDD)      // 16.78M elems
#define WE   ((size_t)HIDD * HIDD)     // 4.19M elems
__device__ float  g_scratch[BUFE * 9 + (size_t)NBT * HH];
__device__ __half g_hf[BUFE * 4 + WE * 6];

__device__ __forceinline__ float sigmoidf_(float x) { return 1.f / (1.f + expf(-x)); }

__device__ __forceinline__ uint32_t smem_u32(const void* p) {
    uint32_t a;
    asm("{ .reg .u64 t; cvta.to.shared.u64 t, %1; cvt.u32.u64 %0, t; }" : "=r"(a) : "l"(p));
    return a;
}
__device__ __forceinline__ void cp16(uint32_t dst, const void* src) {
    asm volatile("cp.async.cg.shared.global [%0], [%1], 16;" :: "r"(dst), "l"(src));
}
__device__ __forceinline__ void cp_commit() {
    asm volatile("cp.async.commit_group;" ::: "memory");
}
__device__ __forceinline__ void ldsm4(uint32_t* r, uint32_t addr) {
    asm volatile("ldmatrix.sync.aligned.m8n8.x4.shared.b16 {%0,%1,%2,%3}, [%4];"
                 : "=r"(r[0]), "=r"(r[1]), "=r"(r[2]), "=r"(r[3]) : "r"(addr));
}
__device__ __forceinline__ void mma16816h(float* c, const uint32_t* a, uint32_t b0, uint32_t b1) {
    asm volatile("mma.sync.aligned.m16n8k16.row.col.f32.f16.f16.f32 "
                 "{%0,%1,%2,%3}, {%4,%5,%6,%7}, {%8,%9}, {%0,%1,%2,%3};"
                 : "+f"(c[0]), "+f"(c[1]), "+f"(c[2]), "+f"(c[3])
                 : "r"(a[0]), "r"(a[1]), "r"(a[2]), "r"(a[3]), "r"(b0), "r"(b1));
}

// ---- packed f32x2 helpers ----
__device__ __forceinline__ uint64_t f32x2_fma(uint64_t a, uint64_t b, uint64_t c) {
    uint64_t d;
    asm("fma.rn.f32x2 %0, %1, %2, %3;" : "=l"(d) : "l"(a), "l"(b), "l"(c));
    return d;
}
__device__ __forceinline__ uint64_t f32x2_mul(uint64_t a, uint64_t b) {
    uint64_t d;
    asm("mul.rn.f32x2 %0, %1, %2;" : "=l"(d) : "l"(a), "l"(b));
    return d;
}
__device__ __forceinline__ uint64_t pack2(float x) {
    uint64_t d; uint32_t u = __float_as_uint(x);
    asm("mov.b64 %0, {%1, %1};" : "=l"(d) : "r"(u));
    return d;
}
__device__ __forceinline__ float unpack_sum(uint64_t p) {
    uint32_t lo, hi;
    asm("mov.b64 {%0, %1}, %2;" : "=r"(lo), "=r"(hi) : "l"(p));
    return __uint_as_float(lo) + __uint_as_float(hi);
}
__device__ __forceinline__ void lds_v2u64(uint64_t& a, uint64_t& b, uint32_t addr) {
    asm volatile("ld.shared.v2.u64 {%0, %1}, [%2];" : "=l"(a), "=l"(b) : "r"(addr));
}

// ======================================================================
// mma.sync GEMM, fp16x2 split: C = (Ah + Al) @ Bh^T.
// A as (Ahi, Alo) [M,K] fp16 row-major; W as Bh [N,K] fp16 (= fp16(W^T)).
// Dropped term A*Bl has RMS rel magnitude ~2^-12 -> end-to-end ~1e-4.
// CTA tile 128x128, BK=32, 3-stage cp.async, 2 CTAs/SM.
// Per-row smem layout: A row = hi bytes 0-63 | lo bytes 64-127;
//                      B row = logical hi only (physical scatter via swizzle).
// ======================================================================
#define GK     2048
#define BK     32
#define NCH    (GK / BK)          // 64
#define SM_A   0
#define SM_B   (16 * 1024)
#define STAGE  (32 * 1024)
#define NSTAGE 3
#define SMEM_GEMM (NSTAGE * STAGE)     // 98304

struct GemmBatch {
    const __half* bh[5];
    const float* bias[5];
    float* C[5];
    int epi[5];
};

__global__ void __launch_bounds__(256, 2)
gemm_fp16x2_kernel(const __half* __restrict__ Ahi, const __half* __restrict__ Alo,
                   GemmBatch gb)
{
    extern __shared__ __align__(1024) char sm[];
    const uint32_t smb = smem_u32(sm);

    const int z    = blockIdx.z;
    const int tid  = threadIdx.x;
    const int wid  = tid >> 5;
    const int lane = tid & 31;
    const int bm   = blockIdx.y * 128;
    const int bn   = blockIdx.x * 128;
    const int wm   = wid & 3;       // M group (4 x 32 rows)
    const int wn   = wid >> 2;      // N group (2 x 64 cols)

    // ---- loader constants (all per-thread invariant) ----
    const int lrow = tid >> 3;          // 0..31  (rows lrow + 32*i)
    const int lseg = tid & 7;           // constant across i
    const bool hiTh = (lseg < 4);
    const uint32_t swz = (uint32_t)((lseg * 16) ^ ((lrow & 7) << 4));
    const uint32_t sw0 = (uint32_t)(lrow * 128) + swz;   // smem offset for i=0
    const size_t   gofs = (size_t)lrow * GK + (lseg & 3) * 8;

    const __half* Aptr = (hiTh ? Ahi : Alo) + (size_t)bm * GK + gofs;
    const __half* Bptr = gb.bh[z] + (size_t)bn * GK + gofs;   // read only if hiTh

    const float* bias = gb.bias[z];
    float* C = gb.C[z];
    const int epi = gb.epi[z];

    uint32_t psbase = smb;     // prefetch slot base (slot 0 first)
    auto prefetch = [&]() {
        const uint32_t pa = psbase + SM_A + sw0;
        const uint32_t pb = psbase + SM_B + sw0;
        #pragma unroll
        for (int i = 0; i < 4; i++) {
            cp16(pa + i * 4096, Aptr + (size_t)i * 32 * GK);
            if (hiTh) cp16(pb + i * 4096, Bptr + (size_t)i * 32 * GK);
        }
        cp_commit();
        Aptr += BK;  Bptr += BK;
        psbase += STAGE;
        if (psbase == smb + NSTAGE * STAGE) psbase = smb;
    };

    prefetch();     // chunk 0 -> slot 0
    prefetch();     // chunk 1 -> slot 1

    float acc[2][8][4];
    #pragma unroll
    for (int i = 0; i < 2; i++)
        #pragma unroll
        for (int j = 0; j < 8; j++)
            #pragma unroll
            for (int q = 0; q < 4; q++) acc[i][j][q] = 0.f;

    // ---- compute-phase constants ----
    const int l16  = lane & 15;
    const uint32_t xorv  = (uint32_t)((lane & 7) << 4);
    const uint32_t chalf = (uint32_t)((lane >> 4) * 16);
    const uint32_t xh0 = (chalf)      ^ xorv;   // kk=0, hi half (bytes 0..63)
    const uint32_t xh1 = (32 + chalf) ^ xorv;   // kk=1, hi
    const uint32_t xl0 = (64 + chalf) ^ xorv;   // kk=0, lo half (A only)
    const uint32_t xl1 = (96 + chalf) ^ xorv;   // kk=1, lo
    const uint32_t aBase = SM_A + (uint32_t)((wm * 32 + l16) << 7);
    const uint32_t bBase = SM_B + (uint32_t)((wn * 64 + l16) << 7);

    uint32_t sbase = smb;
    for (int c = 0; c < NCH; c++) {
        if (c + 1 < NCH) asm volatile("cp.async.wait_group 1;" ::: "memory");
        else             asm volatile("cp.async.wait_group 0;" ::: "memory");
        __syncthreads();
        if (c + 2 < NCH) prefetch();

        const uint32_t sA = sbase + aBase;
        const uint32_t sB = sbase + bBase;
        #pragma unroll
        for (int kk = 0; kk < 2; kk++) {
            const uint32_t xh = kk ? xh1 : xh0;
            const uint32_t xl = kk ? xl1 : xl0;
            const uint32_t sAh = sA + xh, sAl = sA + xl;
            const uint32_t sBh = sB + xh;
            uint32_t ah[2][4], al[2][4];
            ldsm4(ah[0], sAh);
            ldsm4(ah[1], sAh + 2048);
            ldsm4(al[0], sAl);
            ldsm4(al[1], sAl + 2048);
            #pragma unroll
            for (int nt = 0; nt < 4; nt++) {
                uint32_t bh4[4];
                ldsm4(bh4, sBh + nt * 2048);
                #pragma unroll
                for (int mt = 0; mt < 2; mt++) {
                    mma16816h(acc[mt][nt * 2],     ah[mt], bh4[0], bh4[2]);
                    mma16816h(acc[mt][nt * 2 + 1], ah[mt], bh4[1], bh4[3]);
                    mma16816h(acc[mt][nt * 2],     al[mt], bh4[0], bh4[2]);
                    mma16816h(acc[mt][nt * 2 + 1], al[mt], bh4[1], bh4[3]);
                }
            }
        }
        sbase += STAGE;
        if (sbase == smb + NSTAGE * STAGE) sbase = smb;
    }

    // epilogue
    #pragma unroll
    for (int mt = 0; mt < 2; mt++) {
        const int r0 = bm + wm * 32 + mt * 16 + (lane >> 2);
        #pragma unroll
        for (int j = 0; j < 8; j++) {
            const int cc = bn + wn * 64 + j * 8 + (lane & 3) * 2;
            float v0 = acc[mt][j][0], v1 = acc[mt][j][1];
            float v2 = acc[mt][j][2], v3 = acc[mt][j][3];
            if (epi == 1) {
                const float b0 = bias ? bias[cc]     : 0.f;
                const float b1 = bias ? bias[cc + 1] : 0.f;
                v0 = sigmoidf_(v0 + b0); v1 = sigmoidf_(v1 + b1);
                v2 = sigmoidf_(v2 + b0); v3 = sigmoidf_(v3 + b1);
            }
            *(float2*)(C + (size_t)r0 * HIDD + cc)       = make_float2(v0, v1);
            *(float2*)(C + (size_t)(r0 + 8) * HIDD + cc) = make_float2(v2, v3);
        }
    }
}

// ======================================================================
// elementwise fp32 -> (fp16 hi, fp16 lo), 4 elems/thread
// ======================================================================
__global__ void split_kernel(const float* __restrict__ in,
                             __half* __restrict__ hi, __half* __restrict__ lo)
{
    const size_t i = ((size_t)blockIdx.x * blockDim.x + threadIdx.x) * 4;
    const float4 v = *(const float4*)(in + i);
    __half h[4], l[4];
    const float* vp = (const float*)&v;
    #pragma unroll
    for (int j = 0; j < 4; j++) {
        h[j] = __float2half_rn(vp[j]);
        l[j] = __float2half_rn(vp[j] - __half2float(h[j]));
    }
    *(__half2*)(hi + i)     = __half2(h[0], h[1]);
    *(__half2*)(hi + i + 2) = __half2(h[2], h[3]);
    *(__half2*)(lo + i)     = __half2(l[0], l[1]);
    *(__half2*)(lo + i + 2) = __half2(l[2], l[3]);
}

// ======================================================================
// all six W [K=2048, N=2048] f32 -> fp16(W^T) [N, K] in ONE launch
// ======================================================================
struct WSet {
    const float* src[6];
    __half* hi[6];
};
__global__ void transpose_half_all_kernel(WSet ws)
{
    __shared__ float tile[32][33];
    const int z  = blockIdx.z;
    const float* W = ws.src[z];
    __half* hi = ws.hi[z];
    const int tx = threadIdx.x, ty = threadIdx.y;     // (32, 8)
    const int x0 = blockIdx.x * 32, y0 = blockIdx.y * 32;
    #pragma unroll
    for (int j = 0; j < 32; j += 8)
        tile[ty + j][tx] = W[(size_t)(y0 + ty + j) * HIDD + x0 + tx];
    __syncthreads();
    #pragma unroll
    for (int j = 0; j < 32; j += 8) {
        const float v = tile[tx][ty + j];
        hi[(size_t)(x0 + ty + j) * HIDD + y0 + tx] = __float2half_rn(v);
    }
}

// ======================================================================
// beta = sigmoid(x @ Wb + bb)
// ======================================================================
__global__ void beta_kernel(const float* __restrict__ x, const float* __restrict__ Wb,
                            const float* __restrict__ bb, float* __restrict__ out)
{
    const int row = blockIdx.x * 16 + (threadIdx.x >> 4);
    const int col = threadIdx.x & 15;
    const float* xr = x + (size_t)row * HIDD;
    float acc = 0.f;
    for (int k = 0; k < HIDD; k += 4) {
        float4 xv = *(const float4*)(xr + k);
        acc += xv.x * Wb[(k + 0) * HH + col];
        acc += xv.y * Wb[(k + 1) * HH + col];
        acc += xv.z * Wb[(k + 2) * HH + col];
        acc += xv.w * Wb[(k + 3) * HH + col];
    }
    out[(size_t)row * HH + col] = sigmoidf_(acc + bb[col]);
}

// ======================================================================
// 3 causal depthwise convs (K=4) + bias + SiLU (+scale) in one launch,
// 4 channels per thread (float4)
// ======================================================================
struct ConvSet {
    const float* u[3];
    const float* w[3];
    const float* b[3];
    float* y[3];
    float scale[3];
};
__global__ void conv_silu_all_kernel(ConvSet cs)
{
    const int z = blockIdx.z;
    const size_t e = ((size_t)blockIdx.x * blockDim.x + threadIdx.x) * 4;
    const int c = (int)(e & (HIDD - 1));
    const int t = (int)((e >> 11) & (TT - 1));
    const float* u = cs.u[z];
    const float* w = cs.w[z];
    float4 acc = *(const float4*)(cs.b[z] + c);
    const float4 w0 = *(const float4*)(w + (size_t)c * 4);
    const float4 w1 = *(const float4*)(w + (size_t)(c + 1) * 4);
    const float4 w2 = *(const float4*)(w + (size_t)(c + 2) * 4);
    const float4 w3 = *(const float4*)(w + (size_t)(c + 3) * 4);
    const float* w0p = (const float*)&w0;
    const float* w1p = (const float*)&w1;
    const float* w2p = (const float*)&w2;
    const float* w3p = (const float*)&w3;
    #pragma unroll
    for (int j = 0; j < 4; j++) {
        if (t - 3 + j >= 0) {
            const float4 u4 = *(const float4*)(u + e + (ptrdiff_t)(j - 3) * HIDD);
            acc.x += w0p[j] * u4.x;
            acc.y += w1p[j] * u4.y;
            acc.z += w2p[j] * u4.z;
            acc.w += w3p[j] * u4.w;
        }
    }
    const float s = cs.scale[z];
    acc.x = acc.x * sigmoidf_(acc.x) * s;
    acc.y = acc.y * sigmoidf_(acc.y) * s;
    acc.z = acc.z * sigmoidf_(acc.z) * s;
    acc.w = acc.w * sigmoidf_(acc.w) * s;
    *(float4*)(cs.y[z] + e) = acc;
}

// ======================================================================
// Delta-rule scan: f32x2 math + two-step-ahead register prefetch.
// 128 blocks x 256 threads; thread = (v in 0..63, 32-k chunk as 16 f32x2).
// ======================================================================
__global__ void __launch_bounds__(256, 1) scan_kernel(
    const float* __restrict__ q, const float* __restrict__ k,
    const float* __restrict__ v, const float* __restrict__ a,
    const float* __restrict__ beta, float* __restrict__ o)
{
    __shared__ __align__(16) float ksm[2][4 * 36];
    __shared__ __align__(16) float qsm[2][4 * 36];
    __shared__ float vsm[2][64];
    __shared__ float gsm[2][64];
    __shared__ float bsm[2];

    const int blk  = blockIdx.x;
    const int b    = blk >> 5;
    const int h    = (blk >> 1) & 15;
    const int half = blk & 1;

    const int tid = threadIdx.x;
    const int vl  = tid >> 2;
    const int c   = tid & 3;
    const int vg  = half * 64 + vl;

    const int lc  = tid & 127;
    const int lsm = (lc >> 5) * 36 + (lc & 31);

    const size_t baseQK = (size_t)b * TT * HIDD + h * DKK;
    const size_t baseVA = (size_t)b * TT * HIDD + h * DVV;

    uint64_t s2[16];
    #pragma unroll
    for (int i = 0; i < 16; i++) s2[i] = 0ull;

    uint32_t kaddr[2], qaddr[2];
    #pragma unroll
    for (int bb2 = 0; bb2 < 2; bb2++) {
        kaddr[bb2] = smem_u32(&ksm[bb2][c * 36]);
        qaddr[bb2] = smem_u32(&qsm[bb2][c * 36]);
    }

    if (tid < 128) ksm[0][lsm] = k[baseQK + lc];
    else           qsm[0][lsm] = q[baseQK + lc];
    if (tid < 64)            vsm[0][tid]      = v[baseVA + half * 64 + tid];
    else if (tid < 128)      gsm[0][tid - 64] = a[baseVA + half * 64 + (tid - 64)];
    if (tid == 0)            bsm[0] = beta[(size_t)b * TT * HH + h];

    float rA_kq = 0.f, rA_vg = 0.f, rA_b = 0.f;
    {
        const size_t off = (size_t)1 * HIDD;
        rA_kq = (tid < 128) ? k[baseQK + off + lc] : q[baseQK + off + lc];
        if (tid < 64)       rA_vg = v[baseVA + off + half * 64 + tid];
        else if (tid < 128) rA_vg = a[baseVA + off + half * 64 + (tid - 64)];
        if (tid == 0)       rA_b = beta[(size_t)(b * TT + 1) * HH + h];
    }

    for (int t = 0; t < TT; t++) {
        const int buf = t & 1;
        __syncthreads();

        float rB_kq = 0.f, rB_vg = 0.f, rB_b = 0.f;
        if (t + 2 < TT) {
            const size_t off = (size_t)(t + 2) * HIDD;
            rB_kq = (tid < 128) ? k[baseQK + off + lc] : q[baseQK + off + lc];
            if (tid < 64)       rB_vg = v[baseVA + off + half * 64 + tid];
            else if (tid < 128) rB_vg = a[baseVA + off + half * 64 + (tid - 64)];
            if (tid == 0)       rB_b = beta[(size_t)(b * TT + t + 2) * HH + h];
        }

        const float av = gsm[buf][vl];
        const float vt = vsm[buf][vl];
        const float bt = bsm[buf];

        uint64_t kf2[16], q2[16];
        #pragma unroll
        for (int j = 0; j < 8; j++)
            lds_v2u64(kf2[2 * j], kf2[2 * j + 1], kaddr[buf] + j * 16);
        #pragma unroll
        for (int j = 0; j < 8; j++)
            lds_v2u64(q2[2 * j], q2[2 * j + 1], qaddr[buf] + j * 16);

        uint64_t ska = 0ull, skb = 0ull;
        #pragma unroll
        for (int i = 0; i < 8; i++) {
            ska = f32x2_fma(s2[2 * i],     kf2[2 * i],     ska);
            skb = f32x2_fma(s2[2 * i + 1], kf2[2 * i + 1], skb);
        }
        float sk = unpack_sum(ska) + unpack_sum(skb);
        sk += __shfl_xor_sync(0xffffffffu, sk, 1);
        sk += __shfl_xor_sync(0xffffffffu, sk, 2);

        const float d  = bt * (sk - vt);
        const uint64_t dn2 = pack2(-d);
        const uint64_t av2 = pack2(av);

        uint64_t opa = 0ull, opb = 0ull;
        #pragma unroll
        for (int i = 0; i < 8; i++) {
            uint64_t n0 = f32x2_mul(dn2, kf2[2 * i]);
            uint64_t n1 = f32x2_mul(dn2, kf2[2 * i + 1]);
            s2[2 * i]     = f32x2_fma(av2, s2[2 * i],     n0);
            s2[2 * i + 1] = f32x2_fma(av2, s2[2 * i + 1], n1);
            opa = f32x2_fma(s2[2 * i],     q2[2 * i],     opa);
            opb = f32x2_fma(s2[2 * i + 1], q2[2 * i + 1], opb);
        }
        float op = unpack_sum(opa) + unpack_sum(opb);
        op += __shfl_xor_sync(0xffffffffu, op, 1);
        op += __shfl_xor_sync(0xffffffffu, op, 2);
        if (c == 0)
            o[(size_t)(b * TT + t) * HIDD + h * DKK + vg] = op;

        if (t + 1 < TT) {
            const int nb = buf ^ 1;
            if (tid < 128) ksm[nb][lsm] = rA_kq;
            else           qsm[nb][lsm] = rA_kq;
            if (tid < 64)        vsm[nb][tid]      = rA_vg;
            else if (tid < 128)  gsm[nb][tid - 64] = rA_vg;
            if (tid == 0)        bsm[nb] = rA_b;
        }
        rA_kq = rB_kq; rA_vg = rB_vg; rA_b = rB_b;
    }
}

// ======================================================================
// LayerNorm over DV=128 + gate, output split to fp16 hi/lo (final GEMM A)
// ======================================================================
__global__ void ln_gate_kernel(const float* __restrict__ o, const float* __restrict__ g,
                               const float* __restrict__ lnw, const float* __restrict__ lnb,
                               __half* __restrict__ ghi, __half* __restrict__ glo)
{
    const int gw   = (int)(((size_t)blockIdx.x * blockDim.x + threadIdx.x) >> 5);
    const int lane = threadIdx.x & 31;
    const size_t base = (size_t)gw * 128 + lane * 4;
    float4 x = *(const float4*)(o + base);
    float s  = x.x + x.y + x.z + x.w;
    float ss = x.x * x.x + x.y * x.y + x.z * x.z + x.w * x.w;
    #pragma unroll
    for (int m = 16; m > 0; m >>= 1) {
        s  += __shfl_xor_sync(0xffffffffu, s,  m);
        ss += __shfl_xor_sync(0xffffffffu, ss, m);
    }
    const float mu  = s * (1.f / 128.f);
    const float var = ss * (1.f / 128.f) - mu * mu;
    const float inv = rsqrtf(var + EPS_F);
    const float4 wv = *(const float4*)(lnw + lane * 4);
    const float4 bv = *(const float4*)(lnb + lane * 4);
    const float4 gv = *(const float4*)(g + base);
    float r[4];
    r[0] = ((x.x - mu) * inv * wv.x + bv.x) * gv.x;
    r[1] = ((x.y - mu) * inv * wv.y + bv.y) * gv.y;
    r[2] = ((x.z - mu) * inv * wv.z + bv.z) * gv.z;
    r[3] = ((x.w - mu) * inv * wv.w + bv.w) * gv.w;
    __half h[4], l[4];
    #pragma unroll
    for (int i = 0; i < 4; i++) {
        h[i] = __float2half_rn(r[i]);
        l[i] = __float2half_rn(r[i] - __half2float(h[i]));
    }
    *(__half2*)(ghi + base)     = __half2(h[0], h[1]);
    *(__half2*)(ghi + base + 2) = __half2(h[2], h[3]);
    *(__half2*)(glo + base)     = __half2(l[0], l[1]);
    *(__half2*)(glo + base + 2) = __half2(l[2], l[3]);
}

// ======================================================================
// launch
// ======================================================================
extern "C" void kernel_launch(void* const* d_in, const int* in_sizes, int n_in,
                              void* d_out, int out_size)
{
    const float* x       = (const float*)d_in[0];
    const float* Wq      = (const float*)d_in[1];
    const float* Wk      = (const float*)d_in[2];
    const float* Wv      = (const float*)d_in[3];
    const float* Wa      = (const float*)d_in[4];
    const float* ba      = (const float*)d_in[5];
    const float* Wb      = (const float*)d_in[6];
    const float* bb      = (const float*)d_in[7];
    const float* Wg      = (const float*)d_in[8];
    const float* Wo      = (const float*)d_in[9];
    const float* qconv_w = (const float*)d_in[10];
    const float* qconv_b = (const float*)d_in[11];
    const float* kconv_w = (const float*)d_in[12];
    const float* kconv_b = (const float*)d_in[13];
    const float* vconv_w = (const float*)d_in[14];
    const float* vconv_b = (const float*)d_in[15];
    const float* ln_w    = (const float*)d_in[16];
    const float* ln_b    = (const float*)d_in[17];

    void* sp = nullptr;
    cudaGetSymbolAddress(&sp, g_scratch);
    float* fb = (float*)sp;
    float* d_qpre = fb + 0 * BUFE;
    float* d_kpre = fb + 1 * BUFE;
    float* d_vpre = fb + 2 * BUFE;
    float* d_q    = fb + 3 * BUFE;
    float* d_k    = fb + 4 * BUFE;
    float* d_v    = fb + 5 * BUFE;
    float* d_a    = fb + 6 * BUFE;
    float* d_g    = fb + 7 * BUFE;
    float* d_o    = fb + 8 * BUFE;
    float* d_beta = fb + 9 * BUFE;

    void* bp = nullptr;
    cudaGetSymbolAddress(&bp, g_hf);
    __half* hb = (__half*)bp;
    __half* xhi = hb + 0 * BUFE;
    __half* xlo = hb + 1 * BUFE;
    __half* ghi = hb + 2 * BUFE;
    __half* glo = hb + 3 * BUFE;
    __half* wt  = hb + 4 * BUFE;              // 6 x WE: fp16(W^T) per weight
    __half* Wq_h = wt + 0 * WE;
    __half* Wk_h = wt + 1 * WE;
    __half* Wv_h = wt + 2 * WE;
    __half* Wa_h = wt + 3 * WE;
    __half* Wg_h = wt + 4 * WE;
    __half* Wo_h = wt + 5 * WE;

    cudaFuncSetAttribute(gemm_fp16x2_kernel,
                         cudaFuncAttributeMaxDynamicSharedMemorySize, SMEM_GEMM);

    // (1) split x
    split_kernel<<<(int)(BUFE / 4 / 256), 256>>>(x, xhi, xlo);

    // (2) all weight transposes (fp16, hi only)
    WSet ws;
    ws.src[0] = Wq; ws.hi[0] = Wq_h;
    ws.src[1] = Wk; ws.hi[1] = Wk_h;
    ws.src[2] = Wv; ws.hi[2] = Wv_h;
    ws.src[3] = Wa; ws.hi[3] = Wa_h;
    ws.src[4] = Wg; ws.hi[4] = Wg_h;
    ws.src[5] = Wo; ws.hi[5] = Wo_h;
    transpose_half_all_kernel<<<dim3(HIDD / 32, HIDD / 32, 6), dim3(32, 8)>>>(ws);

    // (3) beta
    beta_kernel<<<NBT / 16, 256>>>(x, Wb, bb, d_beta);

    // (4) 5 projections, one batched launch
    GemmBatch gb;
    gb.bh[0] = Wq_h; gb.bias[0] = nullptr; gb.C[0] = d_qpre; gb.epi[0] = 0;
    gb.bh[1] = Wk_h; gb.bias[1] = nullptr; gb.C[1] = d_kpre; gb.epi[1] = 0;
    gb.bh[2] = Wv_h; gb.bias[2] = nullptr; gb.C[2] = d_vpre; gb.epi[2] = 0;
    gb.bh[3] = Wa_h; gb.bias[3] = ba;      gb.C[3] = d_a;    gb.epi[3] = 1;
    gb.bh[4] = Wg_h; gb.bias[4] = nullptr; gb.C[4] = d_g;    gb.epi[4] = 1;
    gemm_fp16x2_kernel<<<dim3(HIDD / 128, NBT / 128, 5), 256, SMEM_GEMM>>>(xhi, xlo, gb);

    // (5) 3 convs, one batched launch
    ConvSet cs;
    cs.u[0] = d_qpre; cs.w[0] = qconv_w; cs.b[0] = qconv_b; cs.y[0] = d_q; cs.scale[0] = 1.f;
    cs.u[1] = d_kpre; cs.w[1] = kconv_w; cs.b[1] = kconv_b; cs.y[1] = d_k; cs.scale[1] = SCALE_F;
    cs.u[2] = d_vpre; cs.w[2] = vconv_w; cs.b[2] = vconv_b; cs.y[2] = d_v; cs.scale[2] = 1.f;
    conv_silu_all_kernel<<<dim3((int)((size_t)NBT * HIDD / 4 / 256), 1, 3), 256>>>(cs);

    // (6) scan
    scan_kernel<<<BB * HH * 2, 256>>>(d_q, d_k, d_v, d_a, d_beta, d_o);

    // (7) LN + gate
    ln_gate_kernel<<<(NBT * HH) / 8, 256>>>(d_o, d_g, ln_w, ln_b, ghi, glo);

    // (8) output GEMM
    GemmBatch gbo = {};
    gbo.bh[0] = Wo_h; gbo.bias[0] = nullptr;
    gbo.C[0] = (float*)d_out; gbo.epi[0] = 0;
    gemm_fp16x2_kernel<<<dim3(HIDD / 128, NBT / 128, 1), 256, SMEM_GEMM>>>(ghi, glo, gbo);

    (void)in_sizes; (void)n_in; (void)out_size;
}